// round 14
// baseline (speedup 1.0000x reference)
#include <cuda_runtime.h>
#include <cuda_bf16.h>
#include <cuda_fp16.h>
#include <math.h>

// Problem constants (from reference)
constexpr int Nn  = 100000;
constexpr int Ee  = 3200000;
constexpr int ET  = Nn + Ee;       // edges + self loops
constexpr int FIN = 165;
constexpr int HID = 64;

// ---------------- scratch (static device allocations; no cudaMalloc) ----------------
__device__ __half g_xl1h[(size_t)Nn * HID];   // fp16 source-transform (gathered by att1)
__device__ float g_xr1[(size_t)Nn * HID];
__device__ float g_h  [(size_t)Nn * HID];     // x@Wlin1+blin1 (lin skip)
__device__ float g_xl2[Nn * 2];
__device__ float g_xr2[Nn * 2];
__device__ float g_lin2[Nn * 2];
__device__ int   g_deg[Nn];
__device__ int   g_incl[Nn];
__device__ int   g_rowptr[Nn + 1];
__device__ int   g_cursor[Nn];
__device__ int   g_bsum[128];
__device__ int   g_boff[128];
__device__ int   g_col[ET];

// ---------------- K0: init degrees (self loop => start at 1) ----------------
__global__ void k_init_deg() {
    int i = blockIdx.x * blockDim.x + threadIdx.x;
    if (i < Nn) g_deg[i] = 1;
}

// ---------------- K1: fused layer-1 triple GEMM — tensor cores (split-bf16 x3) ----------------
// xl1 (fp16 out), xr1, h = x@{Wl1,Wr1,Wlin1} as one [100000 x 165] @ [165 x 192] GEMM
// via mma.sync.m16n8k16.bf16, 3-term split: xh*Wh + xl*Wh + xh*Wl (err ~8e-6).
constexpr int KP     = 176;        // K padded to 11 k-steps of 16
constexpr int KPITCH = 184;        // smem row pitch (bf16 elems) — staggers banks
constexpr int G1_NT  = 1563;       // ceil(100000/64)
constexpr int G1_SMEM = (2 * 192 * KPITCH + 2 * 64 * KPITCH) * 2;  // 188,416 B

#define MMA_BF16(c0, c1, c2, c3, a0, a1, a2, a3, b0, b1) \
    asm volatile("mma.sync.aligned.m16n8k16.row.col.f32.bf16.bf16.f32 " \
        "{%0,%1,%2,%3},{%4,%5,%6,%7},{%8,%9},{%0,%1,%2,%3};" \
        : "+f"(c0), "+f"(c1), "+f"(c2), "+f"(c3) \
        : "r"(a0), "r"(a1), "r"(a2), "r"(a3), "r"(b0), "r"(b1))

__global__ __launch_bounds__(256, 1)
void k_gemm1(const float* __restrict__ x,
             const float* __restrict__ Wl, const float* __restrict__ Wr,
             const float* __restrict__ Wlin, const float* __restrict__ blin) {
    extern __shared__ char smem[];
    __nv_bfloat16* Wth = (__nv_bfloat16*)smem;           // [192][KPITCH] (n-major, k contiguous)
    __nv_bfloat16* Wtl = Wth + 192 * KPITCH;
    __nv_bfloat16* Xh  = Wtl + 192 * KPITCH;             // [64][KPITCH]
    __nv_bfloat16* Xl  = Xh + 64 * KPITCH;
    int tid = threadIdx.x;

    // W split + transpose into smem (once per block)
    for (int idx = tid; idx < 192 * KP; idx += 256) {
        int n = idx / KP, k = idx % KP;
        float v = 0.f;
        if (k < FIN) v = (n < 64) ? Wl[k * 64 + n]
                       : (n < 128) ? Wr[k * 64 + (n - 64)]
                       : Wlin[k * 64 + (n - 128)];
        __nv_bfloat16 h = __float2bfloat16(v);
        __nv_bfloat16 l = __float2bfloat16(v - __bfloat162float(h));
        Wth[n * KPITCH + k] = h;
        Wtl[n * KPITCH + k] = l;
    }

    int lane = tid & 31, w = tid >> 5;
    int mgroup = w & 1;            // 2 row-bands of 32
    int ngroup = w >> 1;           // 4 col-bands of 48
    int n0 = ngroup * 48;
    int lq = lane >> 2;            // lane/4
    int colb = 2 * (lane & 3);     // 2*(lane%4)

    // per-j destination: region 0 -> fp16 xl1h, else fp32 (xr1 / h)
    int   regj[6];
    int   ccj[6];
    float* dstp[6];
    float2 biasj[6];
#pragma unroll
    for (int j = 0; j < 6; j++) {
        int col = n0 + j * 8 + colb;
        int reg = col >> 6, cc = col & 63;
        regj[j] = reg; ccj[j] = cc;
        dstp[j] = ((reg == 1) ? g_xr1 : g_h) + cc;
        biasj[j] = (reg == 2) ? make_float2(blin[cc], blin[cc + 1]) : make_float2(0.f, 0.f);
    }

    for (int tile = blockIdx.x; tile < G1_NT; tile += gridDim.x) {
        int row0 = tile * 64;
        int rows = (Nn - row0 < 64) ? (Nn - row0) : 64;
        __syncthreads();   // previous k-loop done before X overwrite (also fences W fill)

        // X tile split into smem
        for (int idx = tid; idx < 64 * KP; idx += 256) {
            int rr = idx / KP, k = idx % KP;
            float v = (rr < rows && k < FIN) ? x[(size_t)(row0 + rr) * FIN + k] : 0.f;
            __nv_bfloat16 h = __float2bfloat16(v);
            __nv_bfloat16 l = __float2bfloat16(v - __bfloat162float(h));
            Xh[rr * KPITCH + k] = h;
            Xl[rr * KPITCH + k] = l;
        }
        __syncthreads();

        float c[2][6][4];
#pragma unroll
        for (int mt = 0; mt < 2; mt++)
#pragma unroll
            for (int j = 0; j < 6; j++)
#pragma unroll
                for (int q = 0; q < 4; q++) c[mt][j][q] = 0.f;

#pragma unroll
        for (int ks = 0; ks < KP / 16; ks++) {
            int k0 = ks * 16;
            unsigned ah[2][4], al[2][4];
#pragma unroll
            for (int mt = 0; mt < 2; mt++) {
                int r1 = (mgroup * 32 + mt * 16 + lq) * KPITCH + k0 + colb;
                int r2 = r1 + 8 * KPITCH;
                ah[mt][0] = *(const unsigned*)&Xh[r1];
                ah[mt][1] = *(const unsigned*)&Xh[r2];
                ah[mt][2] = *(const unsigned*)&Xh[r1 + 8];
                ah[mt][3] = *(const unsigned*)&Xh[r2 + 8];
                al[mt][0] = *(const unsigned*)&Xl[r1];
                al[mt][1] = *(const unsigned*)&Xl[r2];
                al[mt][2] = *(const unsigned*)&Xl[r1 + 8];
                al[mt][3] = *(const unsigned*)&Xl[r2 + 8];
            }
#pragma unroll
            for (int j = 0; j < 6; j++) {
                int nb = (n0 + j * 8 + lq) * KPITCH + k0 + colb;
                unsigned bh0 = *(const unsigned*)&Wth[nb];
                unsigned bh1 = *(const unsigned*)&Wth[nb + 8];
                unsigned bl0 = *(const unsigned*)&Wtl[nb];
                unsigned bl1 = *(const unsigned*)&Wtl[nb + 8];
#pragma unroll
                for (int mt = 0; mt < 2; mt++) {
                    MMA_BF16(c[mt][j][0], c[mt][j][1], c[mt][j][2], c[mt][j][3],
                             ah[mt][0], ah[mt][1], ah[mt][2], ah[mt][3], bh0, bh1);
                    MMA_BF16(c[mt][j][0], c[mt][j][1], c[mt][j][2], c[mt][j][3],
                             al[mt][0], al[mt][1], al[mt][2], al[mt][3], bh0, bh1);
                    MMA_BF16(c[mt][j][0], c[mt][j][1], c[mt][j][2], c[mt][j][3],
                             ah[mt][0], ah[mt][1], ah[mt][2], ah[mt][3], bl0, bl1);
                }
            }
        }

        // epilogue: c0,c1 -> row, c2,c3 -> row+8 (cols col, col+1)
#pragma unroll
        for (int mt = 0; mt < 2; mt++) {
            int rowa = row0 + mgroup * 32 + mt * 16 + lq;
#pragma unroll
            for (int j = 0; j < 6; j++) {
                if (regj[j] == 0) {
                    __half* hb = g_xl1h + ccj[j];
                    if (rowa < Nn)
                        *(__half2*)(hb + (size_t)rowa * 64) =
                            __floats2half2_rn(c[mt][j][0], c[mt][j][1]);
                    if (rowa + 8 < Nn)
                        *(__half2*)(hb + (size_t)(rowa + 8) * 64) =
                            __floats2half2_rn(c[mt][j][2], c[mt][j][3]);
                } else {
                    if (rowa < Nn)
                        *(float2*)(dstp[j] + (size_t)rowa * 64) =
                            make_float2(c[mt][j][0] + biasj[j].x, c[mt][j][1] + biasj[j].y);
                    if (rowa + 8 < Nn)
                        *(float2*)(dstp[j] + (size_t)(rowa + 8) * 64) =
                            make_float2(c[mt][j][2] + biasj[j].x, c[mt][j][3] + biasj[j].y);
                }
            }
        }
    }
}

// ---------------- K2: degree histogram over real edges ----------------
__global__ void k_deg(const int* __restrict__ ei) {
    int i = blockIdx.x * blockDim.x + threadIdx.x;
    if (i < Ee) {
        int d = ei[Ee + i];     // dst row
        atomicAdd(&g_deg[d], 1);
    }
}

// ---------------- K3: 3-phase exclusive scan -> rowptr, cursor ----------------
__global__ __launch_bounds__(1024) void k_scan1() {
    __shared__ int s[1024];
    int tid = threadIdx.x;
    int i = blockIdx.x * 1024 + tid;
    int v = (i < Nn) ? g_deg[i] : 0;
    s[tid] = v;
    __syncthreads();
    for (int off = 1; off < 1024; off <<= 1) {
        int t = (tid >= off) ? s[tid - off] : 0;
        __syncthreads();
        s[tid] += t;
        __syncthreads();
    }
    if (i < Nn) g_incl[i] = s[tid];
    if (tid == 1023) g_bsum[blockIdx.x] = s[tid];
}

__global__ void k_scan2(int nb) {
    __shared__ int s[128];
    int tid = threadIdx.x;
    int v = (tid < nb) ? g_bsum[tid] : 0;
    s[tid] = v;
    __syncthreads();
    for (int off = 1; off < 128; off <<= 1) {
        int t = (tid >= off) ? s[tid - off] : 0;
        __syncthreads();
        s[tid] += t;
        __syncthreads();
    }
    g_boff[tid] = s[tid] - v;   // exclusive
}

__global__ void k_scan3() {
    int i = blockIdx.x * blockDim.x + threadIdx.x;
    if (i < Nn) {
        int r = g_incl[i] + g_boff[i >> 10];
        g_rowptr[i + 1] = r;
        g_cursor[i] = r - g_deg[i];    // == rowptr[i]
        if (i == 0) g_rowptr[0] = 0;
    }
}

// ---------------- K4: scatter edges + self loops into CSR ----------------
__global__ void k_scatter(const int* __restrict__ ei) {
    int i = blockIdx.x * blockDim.x + threadIdx.x;
    if (i >= ET) return;
    int s, d;
    if (i < Ee) { s = ei[i]; d = ei[Ee + i]; }
    else        { s = d = i - Ee; }
    int pos = atomicAdd(&g_cursor[d], 1);
    g_col[pos] = s;
}

// ---------------- K5: layer-1 attention (fp16 gathers) + FUSED layer-2 transforms ----------------
// Half-warp slots; lane owns 4 channels. xl1 gathered as fp16 (8 B/lane, one
// 128B line per edge — half the L2 traffic of fp32).
__global__ __launch_bounds__(256, 5)
void k_att1(const float* __restrict__ att, const float* __restrict__ b1,
            const float* __restrict__ Wl2, const float* __restrict__ Wr2,
            const float* __restrict__ Wlin2, const float* __restrict__ blin2) {
    int gt = blockIdx.x * blockDim.x + threadIdx.x;
    int i = gt >> 5;
    int lane = gt & 31;
    if (i >= Nn) return;
    int half = lane >> 4;     // edge slot 0/1
    int g = lane & 15;        // channel group (4 channels)

    int e0 = g_rowptr[i], e1 = g_rowptr[i + 1];

    float4 r = ((const float4*)(g_xr1 + (size_t)i * 64))[g];
    float4 a = ((const float4*)att)[g];

    float m = -1e30f, s = 0.f;
    float A0 = 0.f, A1 = 0.f, A2 = 0.f, A3 = 0.f;

    for (int base = e0; base < e1; base += 2) {
        int idx = base + half;
        bool act = idx < e1;
        int j = act ? g_col[idx] : 0;
        uint2 up = ((const uint2*)(g_xl1h + (size_t)j * 64))[g];
        float2 f01 = __half22float2(*(__half2*)&up.x);
        float2 f23 = __half22float2(*(__half2*)&up.y);

        float t0 = f01.x + r.x; t0 = (t0 > 0.f) ? t0 : 0.2f * t0;
        float t1 = f01.y + r.y; t1 = (t1 > 0.f) ? t1 : 0.2f * t1;
        float t2 = f23.x + r.z; t2 = (t2 > 0.f) ? t2 : 0.2f * t2;
        float t3 = f23.y + r.w; t3 = (t3 > 0.f) ? t3 : 0.2f * t3;
        float p = t0 * a.x + t1 * a.y + t2 * a.z + t3 * a.w;
        p += __shfl_xor_sync(0xffffffffu, p, 1);
        p += __shfl_xor_sync(0xffffffffu, p, 2);
        p += __shfl_xor_sync(0xffffffffu, p, 4);
        p += __shfl_xor_sync(0xffffffffu, p, 8);

        if (act) {
            if (p > m) {
                float sc = __expf(m - p);
                s *= sc; A0 *= sc; A1 *= sc; A2 *= sc; A3 *= sc;
                m = p;
            }
            float w = __expf(p - m);
            s += w;
            A0 += w * f01.x; A1 += w * f01.y; A2 += w * f23.x; A3 += w * f23.y;
        }
    }

    // merge the two half-states (xor 16) — both halves end with identical state
    {
        float mo  = __shfl_xor_sync(0xffffffffu, m, 16);
        float so  = __shfl_xor_sync(0xffffffffu, s, 16);
        float B0  = __shfl_xor_sync(0xffffffffu, A0, 16);
        float B1  = __shfl_xor_sync(0xffffffffu, A1, 16);
        float B2  = __shfl_xor_sync(0xffffffffu, A2, 16);
        float B3  = __shfl_xor_sync(0xffffffffu, A3, 16);
        float mn = fmaxf(m, mo);
        float c1 = __expf(m - mn);
        float c2 = __expf(mo - mn);
        s  = s * c1 + so * c2;
        A0 = A0 * c1 + B0 * c2;
        A1 = A1 * c1 + B1 * c2;
        A2 = A2 * c1 + B2 * c2;
        A3 = A3 * c1 + B3 * c2;
    }

    float inv = 1.0f / s;
    float4 bb = ((const float4*)b1)[g];
    float4 hl = ((const float4*)(g_h + (size_t)i * 64))[g];
    float o0 = A0 * inv + bb.x + hl.x;
    float o1 = A1 * inv + bb.y + hl.y;
    float o2 = A2 * inv + bb.z + hl.z;
    float o3 = A3 * inv + bb.w + hl.w;
    o0 = (o0 > 0.f) ? o0 : (__expf(o0) - 1.0f);   // ELU
    o1 = (o1 > 0.f) ? o1 : (__expf(o1) - 1.0f);
    o2 = (o2 > 0.f) ? o2 : (__expf(o2) - 1.0f);
    o3 = (o3 > 0.f) ? o3 : (__expf(o3) - 1.0f);

    // fused layer-2 transforms: partial dots over this lane's 4 channels
    const float2* WlV = (const float2*)Wl2;
    const float2* WrV = (const float2*)Wr2;
    const float2* WnV = (const float2*)Wlin2;
    int c = g * 4;
    float2 wl0 = WlV[c], wl1 = WlV[c + 1], wl2v = WlV[c + 2], wl3 = WlV[c + 3];
    float2 wr0 = WrV[c], wr1 = WrV[c + 1], wr2v = WrV[c + 2], wr3 = WrV[c + 3];
    float2 wn0 = WnV[c], wn1 = WnV[c + 1], wn2v = WnV[c + 2], wn3 = WnV[c + 3];
    float xl_0 = o0 * wl0.x + o1 * wl1.x + o2 * wl2v.x + o3 * wl3.x;
    float xl_1 = o0 * wl0.y + o1 * wl1.y + o2 * wl2v.y + o3 * wl3.y;
    float xr_0 = o0 * wr0.x + o1 * wr1.x + o2 * wr2v.x + o3 * wr3.x;
    float xr_1 = o0 * wr0.y + o1 * wr1.y + o2 * wr2v.y + o3 * wr3.y;
    float ln_0 = o0 * wn0.x + o1 * wn1.x + o2 * wn2v.x + o3 * wn3.x;
    float ln_1 = o0 * wn0.y + o1 * wn1.y + o2 * wn2v.y + o3 * wn3.y;
#pragma unroll
    for (int o = 1; o <= 8; o <<= 1) {
        xl_0 += __shfl_xor_sync(0xffffffffu, xl_0, o);
        xl_1 += __shfl_xor_sync(0xffffffffu, xl_1, o);
        xr_0 += __shfl_xor_sync(0xffffffffu, xr_0, o);
        xr_1 += __shfl_xor_sync(0xffffffffu, xr_1, o);
        ln_0 += __shfl_xor_sync(0xffffffffu, ln_0, o);
        ln_1 += __shfl_xor_sync(0xffffffffu, ln_1, o);
    }
    if (lane == 0) {
        ((float2*)g_xl2)[i] = make_float2(xl_0, xl_1);
        ((float2*)g_xr2)[i] = make_float2(xr_0, xr_1);
        ((float2*)g_lin2)[i] = make_float2(ln_0 + blin2[0], ln_1 + blin2[1]);
    }
}

// ---------------- K7: layer-2 attention, SINGLE PASS + log_softmax ----------------
__global__ void k_att2(const float* __restrict__ att2, const float* __restrict__ b2,
                       float* __restrict__ out) {
    int gt = blockIdx.x * blockDim.x + threadIdx.x;
    int i = gt >> 5;
    int lane = gt & 31;
    if (i >= Nn) return;

    int e0 = g_rowptr[i], e1 = g_rowptr[i + 1];
    const float2* xl2v = (const float2*)g_xl2;
    float2 xr = ((const float2*)g_xr2)[i];
    float a0 = att2[0], a1 = att2[1];

    float m = -1e30f, s = 0.f, A0 = 0.f, A1 = 0.f;
    for (int base = e0; base < e1; base += 32) {
        int idx = base + lane;
        if (idx < e1) {
            int j = g_col[idx];
            float2 xj = xl2v[j];
            float h0 = xj.x + xr.x; h0 = (h0 > 0.f) ? h0 : 0.2f * h0;
            float h1 = xj.y + xr.y; h1 = (h1 > 0.f) ? h1 : 0.2f * h1;
            float e = a0 * h0 + a1 * h1;
            if (e > m) { float sc = __expf(m - e); s *= sc; A0 *= sc; A1 *= sc; m = e; }
            float w = __expf(e - m);
            s += w; A0 += w * xj.x; A1 += w * xj.y;
        }
    }
#pragma unroll
    for (int o = 16; o; o >>= 1) {
        float mo  = __shfl_xor_sync(0xffffffffu, m, o);
        float so  = __shfl_xor_sync(0xffffffffu, s, o);
        float A0o = __shfl_xor_sync(0xffffffffu, A0, o);
        float A1o = __shfl_xor_sync(0xffffffffu, A1, o);
        float mn = fmaxf(m, mo);
        float sc1 = __expf(m - mn);
        float sc2 = __expf(mo - mn);
        s  = s * sc1 + so * sc2;
        A0 = A0 * sc1 + A0o * sc2;
        A1 = A1 * sc1 + A1o * sc2;
        m = mn;
    }

    if (lane == 0) {
        float inv = 1.0f / s;
        float2 ln = ((const float2*)g_lin2)[i];
        float z0 = A0 * inv + b2[0] + ln.x;
        float z1 = A1 * inv + b2[1] + ln.y;
        float zm = fmaxf(z0, z1);
        float l = zm + __logf(__expf(z0 - zm) + __expf(z1 - zm));
        ((float2*)out)[i] = make_float2(z0 - l, z1 - l);
    }
}

// ---------------- K8: edge_index passthrough as float32 values ----------------
__global__ void k_cast_edges(const int* __restrict__ ei, float* __restrict__ out, int n) {
    int i = blockIdx.x * blockDim.x + threadIdx.x;
    if (i < n) out[i] = (float)ei[i];
}

// ---------------- launcher: fork GEMM chain || CSR chain, join before att1 ----------------
extern "C" void kernel_launch(void* const* d_in, const int* in_sizes, int n_in,
                              void* d_out, int out_size) {
    const float* x        = (const float*)d_in[0];
    const float* Wl1      = (const float*)d_in[2];
    const float* Wr1      = (const float*)d_in[3];
    const float* att1     = (const float*)d_in[4];
    const float* b1       = (const float*)d_in[5];
    const float* Wlin1    = (const float*)d_in[6];
    const float* blin1    = (const float*)d_in[7];
    const float* Wl2      = (const float*)d_in[8];
    const float* Wr2      = (const float*)d_in[9];
    const float* att2     = (const float*)d_in[10];
    const float* b2       = (const float*)d_in[11];
    const float* Wlin2    = (const float*)d_in[12];
    const float* blin2    = (const float*)d_in[13];
    float* out = (float*)d_out;

    long long tail_elems = (long long)out_size - (long long)Nn * 2;

    cudaFuncSetAttribute(k_gemm1, cudaFuncAttributeMaxDynamicSharedMemorySize, G1_SMEM);

    int nb = (Nn + 1023) / 1024;   // 98

    // Fork a side stream for the GEMM (independent of CSR build).
    cudaStream_t s2;
    cudaStreamCreateWithFlags(&s2, cudaStreamNonBlocking);
    cudaEvent_t evFork, evJoin;
    cudaEventCreateWithFlags(&evFork, cudaEventDisableTiming);
    cudaEventCreateWithFlags(&evJoin, cudaEventDisableTiming);

    cudaEventRecord(evFork, 0);
    cudaStreamWaitEvent(s2, evFork, 0);

    // side stream: tensor-core GEMM
    k_gemm1<<<152, 256, G1_SMEM, s2>>>(x, Wl1, Wr1, Wlin1, blin1);
    cudaEventRecord(evJoin, s2);

    // main stream: CSR build chain, then output tail (shadowed by gemm1/CSR)
    k_init_deg<<<(Nn + 255) / 256, 256>>>();
    k_deg<<<(Ee + 255) / 256, 256>>>((const int*)d_in[1]);
    k_scan1<<<nb, 1024>>>();
    k_scan2<<<1, 128>>>(nb);
    k_scan3<<<(Nn + 255) / 256, 256>>>();
    k_scatter<<<(ET + 255) / 256, 256>>>((const int*)d_in[1]);
    if (tail_elems > 0) {
        int n = (tail_elems < (long long)2 * Ee) ? (int)tail_elems : 2 * Ee;
        k_cast_edges<<<(n + 255) / 256, 256>>>(
            (const int*)d_in[1], out + (size_t)Nn * 2, n);
    }

    // join: attention needs both GEMM outputs and CSR
    cudaStreamWaitEvent(0, evJoin, 0);
    k_att1<<<(Nn * 32 + 255) / 256, 256>>>(att1, b1, Wl2, Wr2, Wlin2, blin2);
    k_att2<<<(Nn * 32 + 255) / 256, 256>>>(att2, b2, out);

    cudaEventDestroy(evFork);
    cudaEventDestroy(evJoin);
    cudaStreamDestroy(s2);
}

// round 15
// speedup vs baseline: 1.0696x; 1.0696x over previous
#include <cuda_runtime.h>
#include <cuda_bf16.h>
#include <cuda_fp16.h>
#include <math.h>

// Problem constants (from reference)
constexpr int Nn  = 100000;
constexpr int Ee  = 3200000;
constexpr int ET  = Nn + Ee;       // edges + self loops
constexpr int FIN = 165;
constexpr int HID = 64;

// ---------------- scratch (static device allocations; no cudaMalloc) ----------------
__device__ __half g_xl1h[(size_t)Nn * HID];   // fp16 source-transform (gathered by att1)
__device__ float g_xr1[(size_t)Nn * HID];
__device__ float g_h  [(size_t)Nn * HID];     // x@Wlin1+blin1 (lin skip)
__device__ float g_xl2[Nn * 2];
__device__ float g_xr2[Nn * 2];
__device__ float g_lin2[Nn * 2];
__device__ int   g_deg[Nn];
__device__ int   g_incl[Nn];
__device__ int   g_rowptr[Nn + 1];
__device__ int   g_cursor[Nn];
__device__ int   g_bsum[128];
__device__ int   g_boff[128];
__device__ int   g_col[ET];

// ---------------- K0: init degrees (self loop => start at 1) ----------------
__global__ void k_init_deg() {
    int i = blockIdx.x * blockDim.x + threadIdx.x;
    if (i < Nn) g_deg[i] = 1;
}

// ---------------- K1: fused layer-1 triple GEMM — tensor cores (split-bf16 x3) ----------------
constexpr int KP     = 176;        // K padded to 11 k-steps of 16
constexpr int KPITCH = 184;        // smem row pitch (bf16 elems) — staggers banks
constexpr int G1_NT  = 1563;       // ceil(100000/64)
constexpr int G1_SMEM = (2 * 192 * KPITCH + 2 * 64 * KPITCH) * 2;  // 188,416 B

#define MMA_BF16(c0, c1, c2, c3, a0, a1, a2, a3, b0, b1) \
    asm volatile("mma.sync.aligned.m16n8k16.row.col.f32.bf16.bf16.f32 " \
        "{%0,%1,%2,%3},{%4,%5,%6,%7},{%8,%9},{%0,%1,%2,%3};" \
        : "+f"(c0), "+f"(c1), "+f"(c2), "+f"(c3) \
        : "r"(a0), "r"(a1), "r"(a2), "r"(a3), "r"(b0), "r"(b1))

__global__ __launch_bounds__(256, 1)
void k_gemm1(const float* __restrict__ x,
             const float* __restrict__ Wl, const float* __restrict__ Wr,
             const float* __restrict__ Wlin, const float* __restrict__ blin) {
    extern __shared__ char smem[];
    __nv_bfloat16* Wth = (__nv_bfloat16*)smem;           // [192][KPITCH] (n-major, k contiguous)
    __nv_bfloat16* Wtl = Wth + 192 * KPITCH;
    __nv_bfloat16* Xh  = Wtl + 192 * KPITCH;             // [64][KPITCH]
    __nv_bfloat16* Xl  = Xh + 64 * KPITCH;
    int tid = threadIdx.x;

    // W split + transpose into smem (once per block)
    for (int idx = tid; idx < 192 * KP; idx += 256) {
        int n = idx / KP, k = idx % KP;
        float v = 0.f;
        if (k < FIN) v = (n < 64) ? Wl[k * 64 + n]
                       : (n < 128) ? Wr[k * 64 + (n - 64)]
                       : Wlin[k * 64 + (n - 128)];
        __nv_bfloat16 h = __float2bfloat16(v);
        __nv_bfloat16 l = __float2bfloat16(v - __bfloat162float(h));
        Wth[n * KPITCH + k] = h;
        Wtl[n * KPITCH + k] = l;
    }

    int lane = tid & 31, w = tid >> 5;
    int mgroup = w & 1;            // 2 row-bands of 32
    int ngroup = w >> 1;           // 4 col-bands of 48
    int n0 = ngroup * 48;
    int lq = lane >> 2;            // lane/4
    int colb = 2 * (lane & 3);     // 2*(lane%4)

    // per-j destination: region 0 -> fp16 xl1h, else fp32 (xr1 / h)
    int   regj[6];
    int   ccj[6];
    float* dstp[6];
    float2 biasj[6];
#pragma unroll
    for (int j = 0; j < 6; j++) {
        int col = n0 + j * 8 + colb;
        int reg = col >> 6, cc = col & 63;
        regj[j] = reg; ccj[j] = cc;
        dstp[j] = ((reg == 1) ? g_xr1 : g_h) + cc;
        biasj[j] = (reg == 2) ? make_float2(blin[cc], blin[cc + 1]) : make_float2(0.f, 0.f);
    }

    for (int tile = blockIdx.x; tile < G1_NT; tile += gridDim.x) {
        int row0 = tile * 64;
        int rows = (Nn - row0 < 64) ? (Nn - row0) : 64;
        __syncthreads();   // previous k-loop done before X overwrite (also fences W fill)

        // X tile split into smem
        for (int idx = tid; idx < 64 * KP; idx += 256) {
            int rr = idx / KP, k = idx % KP;
            float v = (rr < rows && k < FIN) ? x[(size_t)(row0 + rr) * FIN + k] : 0.f;
            __nv_bfloat16 h = __float2bfloat16(v);
            __nv_bfloat16 l = __float2bfloat16(v - __bfloat162float(h));
            Xh[rr * KPITCH + k] = h;
            Xl[rr * KPITCH + k] = l;
        }
        __syncthreads();

        float c[2][6][4];
#pragma unroll
        for (int mt = 0; mt < 2; mt++)
#pragma unroll
            for (int j = 0; j < 6; j++)
#pragma unroll
                for (int q = 0; q < 4; q++) c[mt][j][q] = 0.f;

#pragma unroll
        for (int ks = 0; ks < KP / 16; ks++) {
            int k0 = ks * 16;
            unsigned ah[2][4], al[2][4];
#pragma unroll
            for (int mt = 0; mt < 2; mt++) {
                int r1 = (mgroup * 32 + mt * 16 + lq) * KPITCH + k0 + colb;
                int r2 = r1 + 8 * KPITCH;
                ah[mt][0] = *(const unsigned*)&Xh[r1];
                ah[mt][1] = *(const unsigned*)&Xh[r2];
                ah[mt][2] = *(const unsigned*)&Xh[r1 + 8];
                ah[mt][3] = *(const unsigned*)&Xh[r2 + 8];
                al[mt][0] = *(const unsigned*)&Xl[r1];
                al[mt][1] = *(const unsigned*)&Xl[r2];
                al[mt][2] = *(const unsigned*)&Xl[r1 + 8];
                al[mt][3] = *(const unsigned*)&Xl[r2 + 8];
            }
#pragma unroll
            for (int j = 0; j < 6; j++) {
                int nb = (n0 + j * 8 + lq) * KPITCH + k0 + colb;
                unsigned bh0 = *(const unsigned*)&Wth[nb];
                unsigned bh1 = *(const unsigned*)&Wth[nb + 8];
                unsigned bl0 = *(const unsigned*)&Wtl[nb];
                unsigned bl1 = *(const unsigned*)&Wtl[nb + 8];
#pragma unroll
                for (int mt = 0; mt < 2; mt++) {
                    MMA_BF16(c[mt][j][0], c[mt][j][1], c[mt][j][2], c[mt][j][3],
                             ah[mt][0], ah[mt][1], ah[mt][2], ah[mt][3], bh0, bh1);
                    MMA_BF16(c[mt][j][0], c[mt][j][1], c[mt][j][2], c[mt][j][3],
                             al[mt][0], al[mt][1], al[mt][2], al[mt][3], bh0, bh1);
                    MMA_BF16(c[mt][j][0], c[mt][j][1], c[mt][j][2], c[mt][j][3],
                             ah[mt][0], ah[mt][1], ah[mt][2], ah[mt][3], bl0, bl1);
                }
            }
        }

        // epilogue: c0,c1 -> row, c2,c3 -> row+8 (cols col, col+1)
#pragma unroll
        for (int mt = 0; mt < 2; mt++) {
            int rowa = row0 + mgroup * 32 + mt * 16 + lq;
#pragma unroll
            for (int j = 0; j < 6; j++) {
                if (regj[j] == 0) {
                    __half* hb = g_xl1h + ccj[j];
                    if (rowa < Nn)
                        *(__half2*)(hb + (size_t)rowa * 64) =
                            __floats2half2_rn(c[mt][j][0], c[mt][j][1]);
                    if (rowa + 8 < Nn)
                        *(__half2*)(hb + (size_t)(rowa + 8) * 64) =
                            __floats2half2_rn(c[mt][j][2], c[mt][j][3]);
                } else {
                    if (rowa < Nn)
                        *(float2*)(dstp[j] + (size_t)rowa * 64) =
                            make_float2(c[mt][j][0] + biasj[j].x, c[mt][j][1] + biasj[j].y);
                    if (rowa + 8 < Nn)
                        *(float2*)(dstp[j] + (size_t)(rowa + 8) * 64) =
                            make_float2(c[mt][j][2] + biasj[j].x, c[mt][j][3] + biasj[j].y);
                }
            }
        }
    }
}

// ---------------- K2: degree histogram over real edges ----------------
__global__ void k_deg(const int* __restrict__ ei) {
    int i = blockIdx.x * blockDim.x + threadIdx.x;
    if (i < Ee) {
        int d = ei[Ee + i];     // dst row
        atomicAdd(&g_deg[d], 1);
    }
}

// ---------------- K3: 3-phase exclusive scan -> rowptr, cursor ----------------
__global__ __launch_bounds__(1024) void k_scan1() {
    __shared__ int s[1024];
    int tid = threadIdx.x;
    int i = blockIdx.x * 1024 + tid;
    int v = (i < Nn) ? g_deg[i] : 0;
    s[tid] = v;
    __syncthreads();
    for (int off = 1; off < 1024; off <<= 1) {
        int t = (tid >= off) ? s[tid - off] : 0;
        __syncthreads();
        s[tid] += t;
        __syncthreads();
    }
    if (i < Nn) g_incl[i] = s[tid];
    if (tid == 1023) g_bsum[blockIdx.x] = s[tid];
}

__global__ void k_scan2(int nb) {
    __shared__ int s[128];
    int tid = threadIdx.x;
    int v = (tid < nb) ? g_bsum[tid] : 0;
    s[tid] = v;
    __syncthreads();
    for (int off = 1; off < 128; off <<= 1) {
        int t = (tid >= off) ? s[tid - off] : 0;
        __syncthreads();
        s[tid] += t;
        __syncthreads();
    }
    g_boff[tid] = s[tid] - v;   // exclusive
}

__global__ void k_scan3() {
    int i = blockIdx.x * blockDim.x + threadIdx.x;
    if (i < Nn) {
        int r = g_incl[i] + g_boff[i >> 10];
        g_rowptr[i + 1] = r;
        g_cursor[i] = r - g_deg[i];    // == rowptr[i]
        if (i == 0) g_rowptr[0] = 0;
    }
}

// ---------------- K4: scatter edges + self loops into CSR ----------------
__global__ void k_scatter(const int* __restrict__ ei) {
    int i = blockIdx.x * blockDim.x + threadIdx.x;
    if (i >= ET) return;
    int s, d;
    if (i < Ee) { s = ei[i]; d = ei[Ee + i]; }
    else        { s = d = i - Ee; }
    int pos = atomicAdd(&g_cursor[d], 1);
    g_col[pos] = s;
}

// ---------------- K5: layer-1 attention (fp16 gathers, 2x unroll) + FUSED l2xform ----------------
// Half-warp slots; lane owns 4 channels. Main loop processes 4 edges (2 per
// half-slot) with both gathers issued before the serial online updates.
__global__ __launch_bounds__(256, 5)
void k_att1(const float* __restrict__ att, const float* __restrict__ b1,
            const float* __restrict__ Wl2, const float* __restrict__ Wr2,
            const float* __restrict__ Wlin2, const float* __restrict__ blin2) {
    int gt = blockIdx.x * blockDim.x + threadIdx.x;
    int i = gt >> 5;
    int lane = gt & 31;
    if (i >= Nn) return;
    int half = lane >> 4;     // edge slot 0/1
    int g = lane & 15;        // channel group (4 channels)

    int e0 = g_rowptr[i], e1 = g_rowptr[i + 1];

    float4 r = ((const float4*)(g_xr1 + (size_t)i * 64))[g];
    float4 a = ((const float4*)att)[g];

    float m = -1e30f, s = 0.f;
    float A0 = 0.f, A1 = 0.f, A2 = 0.f, A3 = 0.f;

    int base = e0;
    for (; base + 3 < e1; base += 4) {
        int idx1 = base + half;
        int idx2 = base + 2 + half;
        int j1 = g_col[idx1];
        int j2 = g_col[idx2];
        uint2 up1 = ((const uint2*)(g_xl1h + (size_t)j1 * 64))[g];
        uint2 up2 = ((const uint2*)(g_xl1h + (size_t)j2 * 64))[g];
        float2 u1a = __half22float2(*(__half2*)&up1.x);
        float2 u1b = __half22float2(*(__half2*)&up1.y);
        float2 u2a = __half22float2(*(__half2*)&up2.x);
        float2 u2b = __half22float2(*(__half2*)&up2.y);

        float t0 = u1a.x + r.x; t0 = (t0 > 0.f) ? t0 : 0.2f * t0;
        float t1 = u1a.y + r.y; t1 = (t1 > 0.f) ? t1 : 0.2f * t1;
        float t2 = u1b.x + r.z; t2 = (t2 > 0.f) ? t2 : 0.2f * t2;
        float t3 = u1b.y + r.w; t3 = (t3 > 0.f) ? t3 : 0.2f * t3;
        float p1 = t0 * a.x + t1 * a.y + t2 * a.z + t3 * a.w;
        float s0 = u2a.x + r.x; s0 = (s0 > 0.f) ? s0 : 0.2f * s0;
        float s1 = u2a.y + r.y; s1 = (s1 > 0.f) ? s1 : 0.2f * s1;
        float s2v = u2b.x + r.z; s2v = (s2v > 0.f) ? s2v : 0.2f * s2v;
        float s3 = u2b.y + r.w; s3 = (s3 > 0.f) ? s3 : 0.2f * s3;
        float p2 = s0 * a.x + s1 * a.y + s2v * a.z + s3 * a.w;
#pragma unroll
        for (int o = 1; o <= 8; o <<= 1) {
            p1 += __shfl_xor_sync(0xffffffffu, p1, o);
            p2 += __shfl_xor_sync(0xffffffffu, p2, o);
        }
        if (p1 > m) { float sc = __expf(m - p1); s *= sc; A0 *= sc; A1 *= sc; A2 *= sc; A3 *= sc; m = p1; }
        float w1 = __expf(p1 - m);
        s += w1; A0 += w1 * u1a.x; A1 += w1 * u1a.y; A2 += w1 * u1b.x; A3 += w1 * u1b.y;
        if (p2 > m) { float sc = __expf(m - p2); s *= sc; A0 *= sc; A1 *= sc; A2 *= sc; A3 *= sc; m = p2; }
        float w2 = __expf(p2 - m);
        s += w2; A0 += w2 * u2a.x; A1 += w2 * u2a.y; A2 += w2 * u2b.x; A3 += w2 * u2b.y;
    }
    for (; base < e1; base += 2) {
        int idx = base + half;
        bool act = idx < e1;
        int j = act ? g_col[idx] : 0;
        uint2 up = ((const uint2*)(g_xl1h + (size_t)j * 64))[g];
        float2 f01 = __half22float2(*(__half2*)&up.x);
        float2 f23 = __half22float2(*(__half2*)&up.y);

        float t0 = f01.x + r.x; t0 = (t0 > 0.f) ? t0 : 0.2f * t0;
        float t1 = f01.y + r.y; t1 = (t1 > 0.f) ? t1 : 0.2f * t1;
        float t2 = f23.x + r.z; t2 = (t2 > 0.f) ? t2 : 0.2f * t2;
        float t3 = f23.y + r.w; t3 = (t3 > 0.f) ? t3 : 0.2f * t3;
        float p = t0 * a.x + t1 * a.y + t2 * a.z + t3 * a.w;
#pragma unroll
        for (int o = 1; o <= 8; o <<= 1)
            p += __shfl_xor_sync(0xffffffffu, p, o);

        if (act) {
            if (p > m) {
                float sc = __expf(m - p);
                s *= sc; A0 *= sc; A1 *= sc; A2 *= sc; A3 *= sc;
                m = p;
            }
            float w = __expf(p - m);
            s += w;
            A0 += w * f01.x; A1 += w * f01.y; A2 += w * f23.x; A3 += w * f23.y;
        }
    }

    // merge the two half-states (xor 16) — both halves end with identical state
    {
        float mo  = __shfl_xor_sync(0xffffffffu, m, 16);
        float so  = __shfl_xor_sync(0xffffffffu, s, 16);
        float B0  = __shfl_xor_sync(0xffffffffu, A0, 16);
        float B1  = __shfl_xor_sync(0xffffffffu, A1, 16);
        float B2  = __shfl_xor_sync(0xffffffffu, A2, 16);
        float B3  = __shfl_xor_sync(0xffffffffu, A3, 16);
        float mn = fmaxf(m, mo);
        float c1 = __expf(m - mn);
        float c2 = __expf(mo - mn);
        s  = s * c1 + so * c2;
        A0 = A0 * c1 + B0 * c2;
        A1 = A1 * c1 + B1 * c2;
        A2 = A2 * c1 + B2 * c2;
        A3 = A3 * c1 + B3 * c2;
    }

    float inv = 1.0f / s;
    float4 bb = ((const float4*)b1)[g];
    float4 hl = ((const float4*)(g_h + (size_t)i * 64))[g];
    float o0 = A0 * inv + bb.x + hl.x;
    float o1 = A1 * inv + bb.y + hl.y;
    float o2 = A2 * inv + bb.z + hl.z;
    float o3 = A3 * inv + bb.w + hl.w;
    o0 = (o0 > 0.f) ? o0 : (__expf(o0) - 1.0f);   // ELU
    o1 = (o1 > 0.f) ? o1 : (__expf(o1) - 1.0f);
    o2 = (o2 > 0.f) ? o2 : (__expf(o2) - 1.0f);
    o3 = (o3 > 0.f) ? o3 : (__expf(o3) - 1.0f);

    // fused layer-2 transforms: partial dots over this lane's 4 channels
    const float2* WlV = (const float2*)Wl2;
    const float2* WrV = (const float2*)Wr2;
    const float2* WnV = (const float2*)Wlin2;
    int c = g * 4;
    float2 wl0 = WlV[c], wl1 = WlV[c + 1], wl2v = WlV[c + 2], wl3 = WlV[c + 3];
    float2 wr0 = WrV[c], wr1 = WrV[c + 1], wr2v = WrV[c + 2], wr3 = WrV[c + 3];
    float2 wn0 = WnV[c], wn1 = WnV[c + 1], wn2v = WnV[c + 2], wn3 = WnV[c + 3];
    float xl_0 = o0 * wl0.x + o1 * wl1.x + o2 * wl2v.x + o3 * wl3.x;
    float xl_1 = o0 * wl0.y + o1 * wl1.y + o2 * wl2v.y + o3 * wl3.y;
    float xr_0 = o0 * wr0.x + o1 * wr1.x + o2 * wr2v.x + o3 * wr3.x;
    float xr_1 = o0 * wr0.y + o1 * wr1.y + o2 * wr2v.y + o3 * wr3.y;
    float ln_0 = o0 * wn0.x + o1 * wn1.x + o2 * wn2v.x + o3 * wn3.x;
    float ln_1 = o0 * wn0.y + o1 * wn1.y + o2 * wn2v.y + o3 * wn3.y;
#pragma unroll
    for (int o = 1; o <= 8; o <<= 1) {
        xl_0 += __shfl_xor_sync(0xffffffffu, xl_0, o);
        xl_1 += __shfl_xor_sync(0xffffffffu, xl_1, o);
        xr_0 += __shfl_xor_sync(0xffffffffu, xr_0, o);
        xr_1 += __shfl_xor_sync(0xffffffffu, xr_1, o);
        ln_0 += __shfl_xor_sync(0xffffffffu, ln_0, o);
        ln_1 += __shfl_xor_sync(0xffffffffu, ln_1, o);
    }
    if (lane == 0) {
        ((float2*)g_xl2)[i] = make_float2(xl_0, xl_1);
        ((float2*)g_xr2)[i] = make_float2(xr_0, xr_1);
        ((float2*)g_lin2)[i] = make_float2(ln_0 + blin2[0], ln_1 + blin2[1]);
    }
}

// ---------------- K7: layer-2 attention, SINGLE PASS + log_softmax ----------------
__global__ void k_att2(const float* __restrict__ att2, const float* __restrict__ b2,
                       float* __restrict__ out) {
    int gt = blockIdx.x * blockDim.x + threadIdx.x;
    int i = gt >> 5;
    int lane = gt & 31;
    if (i >= Nn) return;

    int e0 = g_rowptr[i], e1 = g_rowptr[i + 1];
    const float2* xl2v = (const float2*)g_xl2;
    float2 xr = ((const float2*)g_xr2)[i];
    float a0 = att2[0], a1 = att2[1];

    float m = -1e30f, s = 0.f, A0 = 0.f, A1 = 0.f;
    for (int base = e0; base < e1; base += 32) {
        int idx = base + lane;
        if (idx < e1) {
            int j = g_col[idx];
            float2 xj = xl2v[j];
            float h0 = xj.x + xr.x; h0 = (h0 > 0.f) ? h0 : 0.2f * h0;
            float h1 = xj.y + xr.y; h1 = (h1 > 0.f) ? h1 : 0.2f * h1;
            float e = a0 * h0 + a1 * h1;
            if (e > m) { float sc = __expf(m - e); s *= sc; A0 *= sc; A1 *= sc; m = e; }
            float w = __expf(e - m);
            s += w; A0 += w * xj.x; A1 += w * xj.y;
        }
    }
#pragma unroll
    for (int o = 16; o; o >>= 1) {
        float mo  = __shfl_xor_sync(0xffffffffu, m, o);
        float so  = __shfl_xor_sync(0xffffffffu, s, o);
        float A0o = __shfl_xor_sync(0xffffffffu, A0, o);
        float A1o = __shfl_xor_sync(0xffffffffu, A1, o);
        float mn = fmaxf(m, mo);
        float sc1 = __expf(m - mn);
        float sc2 = __expf(mo - mn);
        s  = s * sc1 + so * sc2;
        A0 = A0 * sc1 + A0o * sc2;
        A1 = A1 * sc1 + A1o * sc2;
        m = mn;
    }

    if (lane == 0) {
        float inv = 1.0f / s;
        float2 ln = ((const float2*)g_lin2)[i];
        float z0 = A0 * inv + b2[0] + ln.x;
        float z1 = A1 * inv + b2[1] + ln.y;
        float zm = fmaxf(z0, z1);
        float l = zm + __logf(__expf(z0 - zm) + __expf(z1 - zm));
        ((float2*)out)[i] = make_float2(z0 - l, z1 - l);
    }
}

// ---------------- K8: edge_index passthrough as float32 values ----------------
__global__ void k_cast_edges(const int* __restrict__ ei, float* __restrict__ out, int n) {
    int i = blockIdx.x * blockDim.x + threadIdx.x;
    if (i < n) out[i] = (float)ei[i];
}

// ---------------- launcher: fork GEMM || CSR; gemm1 submitted 4th for ncu targeting ----------------
extern "C" void kernel_launch(void* const* d_in, const int* in_sizes, int n_in,
                              void* d_out, int out_size) {
    const float* x        = (const float*)d_in[0];
    const float* Wl1      = (const float*)d_in[2];
    const float* Wr1      = (const float*)d_in[3];
    const float* att1     = (const float*)d_in[4];
    const float* b1       = (const float*)d_in[5];
    const float* Wlin1    = (const float*)d_in[6];
    const float* blin1    = (const float*)d_in[7];
    const float* Wl2      = (const float*)d_in[8];
    const float* Wr2      = (const float*)d_in[9];
    const float* att2     = (const float*)d_in[10];
    const float* b2       = (const float*)d_in[11];
    const float* Wlin2    = (const float*)d_in[12];
    const float* blin2    = (const float*)d_in[13];
    float* out = (float*)d_out;

    long long tail_elems = (long long)out_size - (long long)Nn * 2;

    cudaFuncSetAttribute(k_gemm1, cudaFuncAttributeMaxDynamicSharedMemorySize, G1_SMEM);

    int nb = (Nn + 1023) / 1024;   // 98

    cudaStream_t s2;
    cudaStreamCreateWithFlags(&s2, cudaStreamNonBlocking);
    cudaEvent_t evFork, evJoin;
    cudaEventCreateWithFlags(&evFork, cudaEventDisableTiming);
    cudaEventCreateWithFlags(&evJoin, cudaEventDisableTiming);

    // fork s2 at entry: gemm1 depends only on inputs, regardless of submit position
    cudaEventRecord(evFork, 0);
    cudaStreamWaitEvent(s2, evFork, 0);

    // main stream CSR chain starts; gemm1 SUBMITTED 4th so ncu (-s5-c1, empirical
    // capture = 4th submission) finally profiles it. Execution still overlaps.
    k_init_deg<<<(Nn + 255) / 256, 256>>>();                         // sub 1
    k_deg<<<(Ee + 255) / 256, 256>>>((const int*)d_in[1]);           // sub 2
    k_scan1<<<nb, 1024>>>();                                         // sub 3
    k_gemm1<<<152, 256, G1_SMEM, s2>>>(x, Wl1, Wr1, Wlin1, blin1);   // sub 4 <- profiled
    cudaEventRecord(evJoin, s2);
    k_scan2<<<1, 128>>>(nb);                                         // sub 5
    k_scan3<<<(Nn + 255) / 256, 256>>>();                            // sub 6
    k_scatter<<<(ET + 255) / 256, 256>>>((const int*)d_in[1]);       // sub 7
    if (tail_elems > 0) {
        int n = (tail_elems < (long long)2 * Ee) ? (int)tail_elems : 2 * Ee;
        k_cast_edges<<<(n + 255) / 256, 256>>>(
            (const int*)d_in[1], out + (size_t)Nn * 2, n);
    }

    // join: attention needs both GEMM outputs and CSR
    cudaStreamWaitEvent(0, evJoin, 0);
    k_att1<<<(Nn * 32 + 255) / 256, 256>>>(att1, b1, Wl2, Wr2, Wlin2, blin2);
    k_att2<<<(Nn * 32 + 255) / 256, 256>>>(att2, b2, out);

    cudaEventDestroy(evFork);
    cudaEventDestroy(evJoin);
    cudaStreamDestroy(s2);
}

// round 16
// speedup vs baseline: 1.1376x; 1.0636x over previous
#include <cuda_runtime.h>
#include <cuda_bf16.h>
#include <cuda_fp16.h>
#include <math.h>

// Problem constants (from reference)
constexpr int Nn  = 100000;
constexpr int Ee  = 3200000;
constexpr int ET  = Nn + Ee;       // edges + self loops
constexpr int FIN = 165;
constexpr int HID = 64;

// ---------------- scratch (static device allocations; no cudaMalloc) ----------------
__device__ __half g_xl1h[(size_t)Nn * HID];   // fp16 source-transform (gathered by att1)
__device__ float g_xr1[(size_t)Nn * HID];
__device__ float g_h  [(size_t)Nn * HID];     // x@Wlin1+blin1 (lin skip)
__device__ float g_xl2[Nn * 2];
__device__ float g_xr2[Nn * 2];
__device__ float g_lin2[Nn * 2];
__device__ int   g_deg[Nn];
__device__ int   g_incl[Nn];
__device__ int   g_rowptr[Nn + 1];
__device__ int   g_cursor[Nn];
__device__ int   g_bsum[128];
__device__ int   g_boff[128];
__device__ int   g_col[ET];

// ---------------- K0: init degrees (self loop => start at 1) ----------------
__global__ void k_init_deg() {
    int i = blockIdx.x * blockDim.x + threadIdx.x;
    if (i < Nn) g_deg[i] = 1;
}

// ---------------- K1: fused layer-1 triple GEMM — tensor cores (split-bf16 x3) ----------------
// 512 threads / 16 warps per block: same 188KB smem, double the latency hiding.
// Warp tile = 16 rows x 48 cols (4 mgroups x 4 ngroups).
constexpr int KP     = 176;        // K padded to 11 k-steps of 16
constexpr int KPITCH = 184;        // smem row pitch (bf16 elems) — conflict-free stagger
constexpr int G1_NT  = 1563;       // ceil(100000/64)
constexpr int G1_THREADS = 512;
constexpr int G1_SMEM = (2 * 192 * KPITCH + 2 * 64 * KPITCH) * 2;  // 188,416 B

#define MMA_BF16(c0, c1, c2, c3, a0, a1, a2, a3, b0, b1) \
    asm volatile("mma.sync.aligned.m16n8k16.row.col.f32.bf16.bf16.f32 " \
        "{%0,%1,%2,%3},{%4,%5,%6,%7},{%8,%9},{%0,%1,%2,%3};" \
        : "+f"(c0), "+f"(c1), "+f"(c2), "+f"(c3) \
        : "r"(a0), "r"(a1), "r"(a2), "r"(a3), "r"(b0), "r"(b1))

__global__ __launch_bounds__(G1_THREADS, 1)
void k_gemm1(const float* __restrict__ x,
             const float* __restrict__ Wl, const float* __restrict__ Wr,
             const float* __restrict__ Wlin, const float* __restrict__ blin) {
    extern __shared__ char smem[];
    __nv_bfloat16* Wth = (__nv_bfloat16*)smem;           // [192][KPITCH] (n-major, k contiguous)
    __nv_bfloat16* Wtl = Wth + 192 * KPITCH;
    __nv_bfloat16* Xh  = Wtl + 192 * KPITCH;             // [64][KPITCH]
    __nv_bfloat16* Xl  = Xh + 64 * KPITCH;
    int tid = threadIdx.x;

    // W split + transpose into smem (once per block)
    for (int idx = tid; idx < 192 * KP; idx += G1_THREADS) {
        int n = idx / KP, k = idx % KP;
        float v = 0.f;
        if (k < FIN) v = (n < 64) ? Wl[k * 64 + n]
                       : (n < 128) ? Wr[k * 64 + (n - 64)]
                       : Wlin[k * 64 + (n - 128)];
        __nv_bfloat16 h = __float2bfloat16(v);
        __nv_bfloat16 l = __float2bfloat16(v - __bfloat162float(h));
        Wth[n * KPITCH + k] = h;
        Wtl[n * KPITCH + k] = l;
    }

    int lane = tid & 31, w = tid >> 5;
    int mgroup = w & 3;            // 4 row-bands of 16
    int ngroup = w >> 2;           // 4 col-bands of 48
    int n0 = ngroup * 48;
    int lq = lane >> 2;            // lane/4
    int colb = 2 * (lane & 3);     // 2*(lane%4)

    // per-j destination: region 0 -> fp16 xl1h, else fp32 (xr1 / h)
    int   regj[6];
    int   ccj[6];
    float* dstp[6];
    float2 biasj[6];
#pragma unroll
    for (int j = 0; j < 6; j++) {
        int col = n0 + j * 8 + colb;
        int reg = col >> 6, cc = col & 63;
        regj[j] = reg; ccj[j] = cc;
        dstp[j] = ((reg == 1) ? g_xr1 : g_h) + cc;
        biasj[j] = (reg == 2) ? make_float2(blin[cc], blin[cc + 1]) : make_float2(0.f, 0.f);
    }

    for (int tile = blockIdx.x; tile < G1_NT; tile += gridDim.x) {
        int row0 = tile * 64;
        int rows = (Nn - row0 < 64) ? (Nn - row0) : 64;
        __syncthreads();   // previous k-loop done before X overwrite (also fences W fill)

        // X tile split into smem
        for (int idx = tid; idx < 64 * KP; idx += G1_THREADS) {
            int rr = idx / KP, k = idx % KP;
            float v = (rr < rows && k < FIN) ? x[(size_t)(row0 + rr) * FIN + k] : 0.f;
            __nv_bfloat16 h = __float2bfloat16(v);
            __nv_bfloat16 l = __float2bfloat16(v - __bfloat162float(h));
            Xh[rr * KPITCH + k] = h;
            Xl[rr * KPITCH + k] = l;
        }
        __syncthreads();

        float c[6][4];
#pragma unroll
        for (int j = 0; j < 6; j++)
#pragma unroll
            for (int q = 0; q < 4; q++) c[j][q] = 0.f;

#pragma unroll
        for (int ks = 0; ks < KP / 16; ks++) {
            int k0 = ks * 16;
            unsigned ah[4], al[4];
            {
                int r1 = (mgroup * 16 + lq) * KPITCH + k0 + colb;
                int r2 = r1 + 8 * KPITCH;
                ah[0] = *(const unsigned*)&Xh[r1];
                ah[1] = *(const unsigned*)&Xh[r2];
                ah[2] = *(const unsigned*)&Xh[r1 + 8];
                ah[3] = *(const unsigned*)&Xh[r2 + 8];
                al[0] = *(const unsigned*)&Xl[r1];
                al[1] = *(const unsigned*)&Xl[r2];
                al[2] = *(const unsigned*)&Xl[r1 + 8];
                al[3] = *(const unsigned*)&Xl[r2 + 8];
            }
#pragma unroll
            for (int j = 0; j < 6; j++) {
                int nb = (n0 + j * 8 + lq) * KPITCH + k0 + colb;
                unsigned bh0 = *(const unsigned*)&Wth[nb];
                unsigned bh1 = *(const unsigned*)&Wth[nb + 8];
                unsigned bl0 = *(const unsigned*)&Wtl[nb];
                unsigned bl1 = *(const unsigned*)&Wtl[nb + 8];
                MMA_BF16(c[j][0], c[j][1], c[j][2], c[j][3],
                         ah[0], ah[1], ah[2], ah[3], bh0, bh1);
                MMA_BF16(c[j][0], c[j][1], c[j][2], c[j][3],
                         al[0], al[1], al[2], al[3], bh0, bh1);
                MMA_BF16(c[j][0], c[j][1], c[j][2], c[j][3],
                         ah[0], ah[1], ah[2], ah[3], bl0, bl1);
            }
        }

        // epilogue: c0,c1 -> row, c2,c3 -> row+8 (cols col, col+1)
        {
            int rowa = row0 + mgroup * 16 + lq;
#pragma unroll
            for (int j = 0; j < 6; j++) {
                if (regj[j] == 0) {
                    __half* hb = g_xl1h + ccj[j];
                    if (rowa < Nn)
                        *(__half2*)(hb + (size_t)rowa * 64) =
                            __floats2half2_rn(c[j][0], c[j][1]);
                    if (rowa + 8 < Nn)
                        *(__half2*)(hb + (size_t)(rowa + 8) * 64) =
                            __floats2half2_rn(c[j][2], c[j][3]);
                } else {
                    if (rowa < Nn)
                        *(float2*)(dstp[j] + (size_t)rowa * 64) =
                            make_float2(c[j][0] + biasj[j].x, c[j][1] + biasj[j].y);
                    if (rowa + 8 < Nn)
                        *(float2*)(dstp[j] + (size_t)(rowa + 8) * 64) =
                            make_float2(c[j][2] + biasj[j].x, c[j][3] + biasj[j].y);
                }
            }
        }
    }
}

// ---------------- K2: degree histogram over real edges ----------------
__global__ void k_deg(const int* __restrict__ ei) {
    int i = blockIdx.x * blockDim.x + threadIdx.x;
    if (i < Ee) {
        int d = ei[Ee + i];     // dst row
        atomicAdd(&g_deg[d], 1);
    }
}

// ---------------- K3: 3-phase exclusive scan -> rowptr, cursor ----------------
__global__ __launch_bounds__(1024) void k_scan1() {
    __shared__ int s[1024];
    int tid = threadIdx.x;
    int i = blockIdx.x * 1024 + tid;
    int v = (i < Nn) ? g_deg[i] : 0;
    s[tid] = v;
    __syncthreads();
    for (int off = 1; off < 1024; off <<= 1) {
        int t = (tid >= off) ? s[tid - off] : 0;
        __syncthreads();
        s[tid] += t;
        __syncthreads();
    }
    if (i < Nn) g_incl[i] = s[tid];
    if (tid == 1023) g_bsum[blockIdx.x] = s[tid];
}

__global__ void k_scan2(int nb) {
    __shared__ int s[128];
    int tid = threadIdx.x;
    int v = (tid < nb) ? g_bsum[tid] : 0;
    s[tid] = v;
    __syncthreads();
    for (int off = 1; off < 128; off <<= 1) {
        int t = (tid >= off) ? s[tid - off] : 0;
        __syncthreads();
        s[tid] += t;
        __syncthreads();
    }
    g_boff[tid] = s[tid] - v;   // exclusive
}

__global__ void k_scan3() {
    int i = blockIdx.x * blockDim.x + threadIdx.x;
    if (i < Nn) {
        int r = g_incl[i] + g_boff[i >> 10];
        g_rowptr[i + 1] = r;
        g_cursor[i] = r - g_deg[i];    // == rowptr[i]
        if (i == 0) g_rowptr[0] = 0;
    }
}

// ---------------- K4: scatter edges + self loops into CSR ----------------
__global__ void k_scatter(const int* __restrict__ ei) {
    int i = blockIdx.x * blockDim.x + threadIdx.x;
    if (i >= ET) return;
    int s, d;
    if (i < Ee) { s = ei[i]; d = ei[Ee + i]; }
    else        { s = d = i - Ee; }
    int pos = atomicAdd(&g_cursor[d], 1);
    g_col[pos] = s;
}

// ---------------- K5: layer-1 attention (fp16 gathers, 2x unroll) + FUSED l2xform ----------------
__global__ __launch_bounds__(256, 5)
void k_att1(const float* __restrict__ att, const float* __restrict__ b1,
            const float* __restrict__ Wl2, const float* __restrict__ Wr2,
            const float* __restrict__ Wlin2, const float* __restrict__ blin2) {
    int gt = blockIdx.x * blockDim.x + threadIdx.x;
    int i = gt >> 5;
    int lane = gt & 31;
    if (i >= Nn) return;
    int half = lane >> 4;     // edge slot 0/1
    int g = lane & 15;        // channel group (4 channels)

    int e0 = g_rowptr[i], e1 = g_rowptr[i + 1];

    float4 r = ((const float4*)(g_xr1 + (size_t)i * 64))[g];
    float4 a = ((const float4*)att)[g];

    float m = -1e30f, s = 0.f;
    float A0 = 0.f, A1 = 0.f, A2 = 0.f, A3 = 0.f;

    int base = e0;
    for (; base + 3 < e1; base += 4) {
        int idx1 = base + half;
        int idx2 = base + 2 + half;
        int j1 = g_col[idx1];
        int j2 = g_col[idx2];
        uint2 up1 = ((const uint2*)(g_xl1h + (size_t)j1 * 64))[g];
        uint2 up2 = ((const uint2*)(g_xl1h + (size_t)j2 * 64))[g];
        float2 u1a = __half22float2(*(__half2*)&up1.x);
        float2 u1b = __half22float2(*(__half2*)&up1.y);
        float2 u2a = __half22float2(*(__half2*)&up2.x);
        float2 u2b = __half22float2(*(__half2*)&up2.y);

        float t0 = u1a.x + r.x; t0 = (t0 > 0.f) ? t0 : 0.2f * t0;
        float t1 = u1a.y + r.y; t1 = (t1 > 0.f) ? t1 : 0.2f * t1;
        float t2 = u1b.x + r.z; t2 = (t2 > 0.f) ? t2 : 0.2f * t2;
        float t3 = u1b.y + r.w; t3 = (t3 > 0.f) ? t3 : 0.2f * t3;
        float p1 = t0 * a.x + t1 * a.y + t2 * a.z + t3 * a.w;
        float s0 = u2a.x + r.x; s0 = (s0 > 0.f) ? s0 : 0.2f * s0;
        float s1 = u2a.y + r.y; s1 = (s1 > 0.f) ? s1 : 0.2f * s1;
        float s2v = u2b.x + r.z; s2v = (s2v > 0.f) ? s2v : 0.2f * s2v;
        float s3 = u2b.y + r.w; s3 = (s3 > 0.f) ? s3 : 0.2f * s3;
        float p2 = s0 * a.x + s1 * a.y + s2v * a.z + s3 * a.w;
#pragma unroll
        for (int o = 1; o <= 8; o <<= 1) {
            p1 += __shfl_xor_sync(0xffffffffu, p1, o);
            p2 += __shfl_xor_sync(0xffffffffu, p2, o);
        }
        if (p1 > m) { float sc = __expf(m - p1); s *= sc; A0 *= sc; A1 *= sc; A2 *= sc; A3 *= sc; m = p1; }
        float w1 = __expf(p1 - m);
        s += w1; A0 += w1 * u1a.x; A1 += w1 * u1a.y; A2 += w1 * u1b.x; A3 += w1 * u1b.y;
        if (p2 > m) { float sc = __expf(m - p2); s *= sc; A0 *= sc; A1 *= sc; A2 *= sc; A3 *= sc; m = p2; }
        float w2 = __expf(p2 - m);
        s += w2; A0 += w2 * u2a.x; A1 += w2 * u2a.y; A2 += w2 * u2b.x; A3 += w2 * u2b.y;
    }
    for (; base < e1; base += 2) {
        int idx = base + half;
        bool act = idx < e1;
        int j = act ? g_col[idx] : 0;
        uint2 up = ((const uint2*)(g_xl1h + (size_t)j * 64))[g];
        float2 f01 = __half22float2(*(__half2*)&up.x);
        float2 f23 = __half22float2(*(__half2*)&up.y);

        float t0 = f01.x + r.x; t0 = (t0 > 0.f) ? t0 : 0.2f * t0;
        float t1 = f01.y + r.y; t1 = (t1 > 0.f) ? t1 : 0.2f * t1;
        float t2 = f23.x + r.z; t2 = (t2 > 0.f) ? t2 : 0.2f * t2;
        float t3 = f23.y + r.w; t3 = (t3 > 0.f) ? t3 : 0.2f * t3;
        float p = t0 * a.x + t1 * a.y + t2 * a.z + t3 * a.w;
#pragma unroll
        for (int o = 1; o <= 8; o <<= 1)
            p += __shfl_xor_sync(0xffffffffu, p, o);

        if (act) {
            if (p > m) {
                float sc = __expf(m - p);
                s *= sc; A0 *= sc; A1 *= sc; A2 *= sc; A3 *= sc;
                m = p;
            }
            float w = __expf(p - m);
            s += w;
            A0 += w * f01.x; A1 += w * f01.y; A2 += w * f23.x; A3 += w * f23.y;
        }
    }

    // merge the two half-states (xor 16) — both halves end with identical state
    {
        float mo  = __shfl_xor_sync(0xffffffffu, m, 16);
        float so  = __shfl_xor_sync(0xffffffffu, s, 16);
        float B0  = __shfl_xor_sync(0xffffffffu, A0, 16);
        float B1  = __shfl_xor_sync(0xffffffffu, A1, 16);
        float B2  = __shfl_xor_sync(0xffffffffu, A2, 16);
        float B3  = __shfl_xor_sync(0xffffffffu, A3, 16);
        float mn = fmaxf(m, mo);
        float c1 = __expf(m - mn);
        float c2 = __expf(mo - mn);
        s  = s * c1 + so * c2;
        A0 = A0 * c1 + B0 * c2;
        A1 = A1 * c1 + B1 * c2;
        A2 = A2 * c1 + B2 * c2;
        A3 = A3 * c1 + B3 * c2;
    }

    float inv = 1.0f / s;
    float4 bb = ((const float4*)b1)[g];
    float4 hl = ((const float4*)(g_h + (size_t)i * 64))[g];
    float o0 = A0 * inv + bb.x + hl.x;
    float o1 = A1 * inv + bb.y + hl.y;
    float o2 = A2 * inv + bb.z + hl.z;
    float o3 = A3 * inv + bb.w + hl.w;
    o0 = (o0 > 0.f) ? o0 : (__expf(o0) - 1.0f);   // ELU
    o1 = (o1 > 0.f) ? o1 : (__expf(o1) - 1.0f);
    o2 = (o2 > 0.f) ? o2 : (__expf(o2) - 1.0f);
    o3 = (o3 > 0.f) ? o3 : (__expf(o3) - 1.0f);

    // fused layer-2 transforms: partial dots over this lane's 4 channels
    const float2* WlV = (const float2*)Wl2;
    const float2* WrV = (const float2*)Wr2;
    const float2* WnV = (const float2*)Wlin2;
    int c = g * 4;
    float2 wl0 = WlV[c], wl1 = WlV[c + 1], wl2v = WlV[c + 2], wl3 = WlV[c + 3];
    float2 wr0 = WrV[c], wr1 = WrV[c + 1], wr2v = WrV[c + 2], wr3 = WrV[c + 3];
    float2 wn0 = WnV[c], wn1 = WnV[c + 1], wn2v = WnV[c + 2], wn3 = WnV[c + 3];
    float xl_0 = o0 * wl0.x + o1 * wl1.x + o2 * wl2v.x + o3 * wl3.x;
    float xl_1 = o0 * wl0.y + o1 * wl1.y + o2 * wl2v.y + o3 * wl3.y;
    float xr_0 = o0 * wr0.x + o1 * wr1.x + o2 * wr2v.x + o3 * wr3.x;
    float xr_1 = o0 * wr0.y + o1 * wr1.y + o2 * wr2v.y + o3 * wr3.y;
    float ln_0 = o0 * wn0.x + o1 * wn1.x + o2 * wn2v.x + o3 * wn3.x;
    float ln_1 = o0 * wn0.y + o1 * wn1.y + o2 * wn2v.y + o3 * wn3.y;
#pragma unroll
    for (int o = 1; o <= 8; o <<= 1) {
        xl_0 += __shfl_xor_sync(0xffffffffu, xl_0, o);
        xl_1 += __shfl_xor_sync(0xffffffffu, xl_1, o);
        xr_0 += __shfl_xor_sync(0xffffffffu, xr_0, o);
        xr_1 += __shfl_xor_sync(0xffffffffu, xr_1, o);
        ln_0 += __shfl_xor_sync(0xffffffffu, ln_0, o);
        ln_1 += __shfl_xor_sync(0xffffffffu, ln_1, o);
    }
    if (lane == 0) {
        ((float2*)g_xl2)[i] = make_float2(xl_0, xl_1);
        ((float2*)g_xr2)[i] = make_float2(xr_0, xr_1);
        ((float2*)g_lin2)[i] = make_float2(ln_0 + blin2[0], ln_1 + blin2[1]);
    }
}

// ---------------- K7: layer-2 attention, SINGLE PASS + log_softmax ----------------
__global__ void k_att2(const float* __restrict__ att2, const float* __restrict__ b2,
                       float* __restrict__ out) {
    int gt = blockIdx.x * blockDim.x + threadIdx.x;
    int i = gt >> 5;
    int lane = gt & 31;
    if (i >= Nn) return;

    int e0 = g_rowptr[i], e1 = g_rowptr[i + 1];
    const float2* xl2v = (const float2*)g_xl2;
    float2 xr = ((const float2*)g_xr2)[i];
    float a0 = att2[0], a1 = att2[1];

    float m = -1e30f, s = 0.f, A0 = 0.f, A1 = 0.f;
    for (int base = e0; base < e1; base += 32) {
        int idx = base + lane;
        if (idx < e1) {
            int j = g_col[idx];
            float2 xj = xl2v[j];
            float h0 = xj.x + xr.x; h0 = (h0 > 0.f) ? h0 : 0.2f * h0;
            float h1 = xj.y + xr.y; h1 = (h1 > 0.f) ? h1 : 0.2f * h1;
            float e = a0 * h0 + a1 * h1;
            if (e > m) { float sc = __expf(m - e); s *= sc; A0 *= sc; A1 *= sc; m = e; }
            float w = __expf(e - m);
            s += w; A0 += w * xj.x; A1 += w * xj.y;
        }
    }
#pragma unroll
    for (int o = 16; o; o >>= 1) {
        float mo  = __shfl_xor_sync(0xffffffffu, m, o);
        float so  = __shfl_xor_sync(0xffffffffu, s, o);
        float A0o = __shfl_xor_sync(0xffffffffu, A0, o);
        float A1o = __shfl_xor_sync(0xffffffffu, A1, o);
        float mn = fmaxf(m, mo);
        float sc1 = __expf(m - mn);
        float sc2 = __expf(mo - mn);
        s  = s * sc1 + so * sc2;
        A0 = A0 * sc1 + A0o * sc2;
        A1 = A1 * sc1 + A1o * sc2;
        m = mn;
    }

    if (lane == 0) {
        float inv = 1.0f / s;
        float2 ln = ((const float2*)g_lin2)[i];
        float z0 = A0 * inv + b2[0] + ln.x;
        float z1 = A1 * inv + b2[1] + ln.y;
        float zm = fmaxf(z0, z1);
        float l = zm + __logf(__expf(z0 - zm) + __expf(z1 - zm));
        ((float2*)out)[i] = make_float2(z0 - l, z1 - l);
    }
}

// ---------------- K8: edge_index passthrough as float32 values ----------------
__global__ void k_cast_edges(const int* __restrict__ ei, float* __restrict__ out, int n) {
    int i = blockIdx.x * blockDim.x + threadIdx.x;
    if (i < n) out[i] = (float)ei[i];
}

// ---------------- launcher: fork GEMM || CSR; gemm1 submitted 4th for ncu targeting ----------------
extern "C" void kernel_launch(void* const* d_in, const int* in_sizes, int n_in,
                              void* d_out, int out_size) {
    const float* x        = (const float*)d_in[0];
    const float* Wl1      = (const float*)d_in[2];
    const float* Wr1      = (const float*)d_in[3];
    const float* att1     = (const float*)d_in[4];
    const float* b1       = (const float*)d_in[5];
    const float* Wlin1    = (const float*)d_in[6];
    const float* blin1    = (const float*)d_in[7];
    const float* Wl2      = (const float*)d_in[8];
    const float* Wr2      = (const float*)d_in[9];
    const float* att2     = (const float*)d_in[10];
    const float* b2       = (const float*)d_in[11];
    const float* Wlin2    = (const float*)d_in[12];
    const float* blin2    = (const float*)d_in[13];
    float* out = (float*)d_out;

    long long tail_elems = (long long)out_size - (long long)Nn * 2;

    cudaFuncSetAttribute(k_gemm1, cudaFuncAttributeMaxDynamicSharedMemorySize, G1_SMEM);

    int nb = (Nn + 1023) / 1024;   // 98

    cudaStream_t s2;
    cudaStreamCreateWithFlags(&s2, cudaStreamNonBlocking);
    cudaEvent_t evFork, evJoin;
    cudaEventCreateWithFlags(&evFork, cudaEventDisableTiming);
    cudaEventCreateWithFlags(&evJoin, cudaEventDisableTiming);

    // fork s2 at entry: gemm1 depends only on inputs, regardless of submit position
    cudaEventRecord(evFork, 0);
    cudaStreamWaitEvent(s2, evFork, 0);

    // main stream CSR chain starts; gemm1 SUBMITTED 4th so ncu (-s5-c1) profiles it.
    k_init_deg<<<(Nn + 255) / 256, 256>>>();                         // sub 1
    k_deg<<<(Ee + 255) / 256, 256>>>((const int*)d_in[1]);           // sub 2
    k_scan1<<<nb, 1024>>>();                                         // sub 3
    k_gemm1<<<152, G1_THREADS, G1_SMEM, s2>>>(x, Wl1, Wr1, Wlin1, blin1);  // sub 4 <- profiled
    cudaEventRecord(evJoin, s2);
    k_scan2<<<1, 128>>>(nb);                                         // sub 5
    k_scan3<<<(Nn + 255) / 256, 256>>>();                            // sub 6
    k_scatter<<<(ET + 255) / 256, 256>>>((const int*)d_in[1]);       // sub 7
    if (tail_elems > 0) {
        int n = (tail_elems < (long long)2 * Ee) ? (int)tail_elems : 2 * Ee;
        k_cast_edges<<<(n + 255) / 256, 256>>>(
            (const int*)d_in[1], out + (size_t)Nn * 2, n);
    }

    // join: attention needs both GEMM outputs and CSR
    cudaStreamWaitEvent(0, evJoin, 0);
    k_att1<<<(Nn * 32 + 255) / 256, 256>>>(att1, b1, Wl2, Wr2, Wlin2, blin2);
    k_att2<<<(Nn * 32 + 255) / 256, 256>>>(att2, b2, out);

    cudaEventDestroy(evFork);
    cudaEventDestroy(evJoin);
    cudaStreamDestroy(s2);
}

// round 17
// speedup vs baseline: 1.1606x; 1.0202x over previous
#include <cuda_runtime.h>
#include <cuda_bf16.h>
#include <cuda_fp16.h>
#include <math.h>

// Problem constants (from reference)
constexpr int Nn  = 100000;
constexpr int Ee  = 3200000;
constexpr int ET  = Nn + Ee;       // edges + self loops
constexpr int FIN = 165;
constexpr int HID = 64;

// ---------------- scratch (static device allocations; no cudaMalloc) ----------------
__device__ __half g_xl1h[(size_t)Nn * HID];   // fp16 source-transform (gathered by att1)
__device__ float g_xr1[(size_t)Nn * HID];
__device__ float g_h  [(size_t)Nn * HID];     // x@Wlin1+blin1 (lin skip)
__device__ float g_xl2[Nn * 2];
__device__ float g_xr2[Nn * 2];
__device__ float g_lin2[Nn * 2];
__device__ int   g_deg[Nn];
__device__ int   g_incl[Nn];
__device__ int   g_rowptr[Nn + 1];
__device__ int   g_cursor[Nn];
__device__ int   g_bsum[128];
__device__ int   g_boff[128];
__device__ int   g_col[ET];

// ---------------- K0: init degrees (self loop => start at 1) ----------------
__global__ void k_init_deg() {
    int i = blockIdx.x * blockDim.x + threadIdx.x;
    if (i < Nn) g_deg[i] = 1;
}

// ---------------- K1: fused layer-1 triple GEMM — tensor cores (split-bf16 x3) ----------------
// 1024 threads / 32 warps per block: same 188KB smem, 50% thread occupancy.
// Warp tile = 16 rows x 24 cols (4 mgroups x 8 ngroups, 3 j-fragments each).
constexpr int KP     = 176;        // K padded to 11 k-steps of 16
constexpr int KPITCH = 184;        // smem row pitch (bf16 elems) — conflict-free stagger
constexpr int G1_NT  = 1563;       // ceil(100000/64)
constexpr int G1_THREADS = 1024;
constexpr int G1_SMEM = (2 * 192 * KPITCH + 2 * 64 * KPITCH) * 2;  // 188,416 B

#define MMA_BF16(c0, c1, c2, c3, a0, a1, a2, a3, b0, b1) \
    asm volatile("mma.sync.aligned.m16n8k16.row.col.f32.bf16.bf16.f32 " \
        "{%0,%1,%2,%3},{%4,%5,%6,%7},{%8,%9},{%0,%1,%2,%3};" \
        : "+f"(c0), "+f"(c1), "+f"(c2), "+f"(c3) \
        : "r"(a0), "r"(a1), "r"(a2), "r"(a3), "r"(b0), "r"(b1))

__global__ __launch_bounds__(G1_THREADS, 1)
void k_gemm1(const float* __restrict__ x,
             const float* __restrict__ Wl, const float* __restrict__ Wr,
             const float* __restrict__ Wlin, const float* __restrict__ blin) {
    extern __shared__ char smem[];
    __nv_bfloat16* Wth = (__nv_bfloat16*)smem;           // [192][KPITCH] (n-major, k contiguous)
    __nv_bfloat16* Wtl = Wth + 192 * KPITCH;
    __nv_bfloat16* Xh  = Wtl + 192 * KPITCH;             // [64][KPITCH]
    __nv_bfloat16* Xl  = Xh + 64 * KPITCH;
    int tid = threadIdx.x;

    // W split + transpose into smem (once per block)
    for (int idx = tid; idx < 192 * KP; idx += G1_THREADS) {
        int n = idx / KP, k = idx % KP;
        float v = 0.f;
        if (k < FIN) v = (n < 64) ? Wl[k * 64 + n]
                       : (n < 128) ? Wr[k * 64 + (n - 64)]
                       : Wlin[k * 64 + (n - 128)];
        __nv_bfloat16 h = __float2bfloat16(v);
        __nv_bfloat16 l = __float2bfloat16(v - __bfloat162float(h));
        Wth[n * KPITCH + k] = h;
        Wtl[n * KPITCH + k] = l;
    }

    int lane = tid & 31, w = tid >> 5;
    int mgroup = w & 3;            // 4 row-bands of 16
    int ngroup = w >> 2;           // 8 col-bands of 24
    int n0 = ngroup * 24;
    int lq = lane >> 2;            // lane/4
    int colb = 2 * (lane & 3);     // 2*(lane%4)

    // per-j destination: region 0 -> fp16 xl1h, else fp32 (xr1 / h)
    int   regj[3];
    int   ccj[3];
    float* dstp[3];
    float2 biasj[3];
#pragma unroll
    for (int j = 0; j < 3; j++) {
        int col = n0 + j * 8 + colb;
        int reg = col >> 6, cc = col & 63;
        regj[j] = reg; ccj[j] = cc;
        dstp[j] = ((reg == 1) ? g_xr1 : g_h) + cc;
        biasj[j] = (reg == 2) ? make_float2(blin[cc], blin[cc + 1]) : make_float2(0.f, 0.f);
    }

    for (int tile = blockIdx.x; tile < G1_NT; tile += gridDim.x) {
        int row0 = tile * 64;
        int rows = (Nn - row0 < 64) ? (Nn - row0) : 64;
        __syncthreads();   // previous k-loop done before X overwrite (also fences W fill)

        // X tile split into smem
        for (int idx = tid; idx < 64 * KP; idx += G1_THREADS) {
            int rr = idx / KP, k = idx % KP;
            float v = (rr < rows && k < FIN) ? x[(size_t)(row0 + rr) * FIN + k] : 0.f;
            __nv_bfloat16 h = __float2bfloat16(v);
            __nv_bfloat16 l = __float2bfloat16(v - __bfloat162float(h));
            Xh[rr * KPITCH + k] = h;
            Xl[rr * KPITCH + k] = l;
        }
        __syncthreads();

        float c[3][4];
#pragma unroll
        for (int j = 0; j < 3; j++)
#pragma unroll
            for (int q = 0; q < 4; q++) c[j][q] = 0.f;

#pragma unroll
        for (int ks = 0; ks < KP / 16; ks++) {
            int k0 = ks * 16;
            unsigned ah[4], al[4];
            {
                int r1 = (mgroup * 16 + lq) * KPITCH + k0 + colb;
                int r2 = r1 + 8 * KPITCH;
                ah[0] = *(const unsigned*)&Xh[r1];
                ah[1] = *(const unsigned*)&Xh[r2];
                ah[2] = *(const unsigned*)&Xh[r1 + 8];
                ah[3] = *(const unsigned*)&Xh[r2 + 8];
                al[0] = *(const unsigned*)&Xl[r1];
                al[1] = *(const unsigned*)&Xl[r2];
                al[2] = *(const unsigned*)&Xl[r1 + 8];
                al[3] = *(const unsigned*)&Xl[r2 + 8];
            }
#pragma unroll
            for (int j = 0; j < 3; j++) {
                int nb = (n0 + j * 8 + lq) * KPITCH + k0 + colb;
                unsigned bh0 = *(const unsigned*)&Wth[nb];
                unsigned bh1 = *(const unsigned*)&Wth[nb + 8];
                unsigned bl0 = *(const unsigned*)&Wtl[nb];
                unsigned bl1 = *(const unsigned*)&Wtl[nb + 8];
                MMA_BF16(c[j][0], c[j][1], c[j][2], c[j][3],
                         ah[0], ah[1], ah[2], ah[3], bh0, bh1);
                MMA_BF16(c[j][0], c[j][1], c[j][2], c[j][3],
                         al[0], al[1], al[2], al[3], bh0, bh1);
                MMA_BF16(c[j][0], c[j][1], c[j][2], c[j][3],
                         ah[0], ah[1], ah[2], ah[3], bl0, bl1);
            }
        }

        // epilogue: c0,c1 -> row, c2,c3 -> row+8 (cols col, col+1)
        {
            int rowa = row0 + mgroup * 16 + lq;
#pragma unroll
            for (int j = 0; j < 3; j++) {
                if (regj[j] == 0) {
                    __half* hb = g_xl1h + ccj[j];
                    if (rowa < Nn)
                        *(__half2*)(hb + (size_t)rowa * 64) =
                            __floats2half2_rn(c[j][0], c[j][1]);
                    if (rowa + 8 < Nn)
                        *(__half2*)(hb + (size_t)(rowa + 8) * 64) =
                            __floats2half2_rn(c[j][2], c[j][3]);
                } else {
                    if (rowa < Nn)
                        *(float2*)(dstp[j] + (size_t)rowa * 64) =
                            make_float2(c[j][0] + biasj[j].x, c[j][1] + biasj[j].y);
                    if (rowa + 8 < Nn)
                        *(float2*)(dstp[j] + (size_t)(rowa + 8) * 64) =
                            make_float2(c[j][2] + biasj[j].x, c[j][3] + biasj[j].y);
                }
            }
        }
    }
}

// ---------------- K2: degree histogram over real edges ----------------
__global__ void k_deg(const int* __restrict__ ei) {
    int i = blockIdx.x * blockDim.x + threadIdx.x;
    if (i < Ee) {
        int d = ei[Ee + i];     // dst row
        atomicAdd(&g_deg[d], 1);
    }
}

// ---------------- K3: 3-phase exclusive scan -> rowptr, cursor ----------------
__global__ __launch_bounds__(1024) void k_scan1() {
    __shared__ int s[1024];
    int tid = threadIdx.x;
    int i = blockIdx.x * 1024 + tid;
    int v = (i < Nn) ? g_deg[i] : 0;
    s[tid] = v;
    __syncthreads();
    for (int off = 1; off < 1024; off <<= 1) {
        int t = (tid >= off) ? s[tid - off] : 0;
        __syncthreads();
        s[tid] += t;
        __syncthreads();
    }
    if (i < Nn) g_incl[i] = s[tid];
    if (tid == 1023) g_bsum[blockIdx.x] = s[tid];
}

__global__ void k_scan2(int nb) {
    __shared__ int s[128];
    int tid = threadIdx.x;
    int v = (tid < nb) ? g_bsum[tid] : 0;
    s[tid] = v;
    __syncthreads();
    for (int off = 1; off < 128; off <<= 1) {
        int t = (tid >= off) ? s[tid - off] : 0;
        __syncthreads();
        s[tid] += t;
        __syncthreads();
    }
    g_boff[tid] = s[tid] - v;   // exclusive
}

__global__ void k_scan3() {
    int i = blockIdx.x * blockDim.x + threadIdx.x;
    if (i < Nn) {
        int r = g_incl[i] + g_boff[i >> 10];
        g_rowptr[i + 1] = r;
        g_cursor[i] = r - g_deg[i];    // == rowptr[i]
        if (i == 0) g_rowptr[0] = 0;
    }
}

// ---------------- K4: scatter edges + self loops into CSR ----------------
__global__ void k_scatter(const int* __restrict__ ei) {
    int i = blockIdx.x * blockDim.x + threadIdx.x;
    if (i >= ET) return;
    int s, d;
    if (i < Ee) { s = ei[i]; d = ei[Ee + i]; }
    else        { s = d = i - Ee; }
    int pos = atomicAdd(&g_cursor[d], 1);
    g_col[pos] = s;
}

// ---------------- K5: layer-1 attention (fp16 gathers, 2x unroll) + FUSED l2xform ----------------
__global__ __launch_bounds__(256, 5)
void k_att1(const float* __restrict__ att, const float* __restrict__ b1,
            const float* __restrict__ Wl2, const float* __restrict__ Wr2,
            const float* __restrict__ Wlin2, const float* __restrict__ blin2) {
    int gt = blockIdx.x * blockDim.x + threadIdx.x;
    int i = gt >> 5;
    int lane = gt & 31;
    if (i >= Nn) return;
    int half = lane >> 4;     // edge slot 0/1
    int g = lane & 15;        // channel group (4 channels)

    int e0 = g_rowptr[i], e1 = g_rowptr[i + 1];

    float4 r = ((const float4*)(g_xr1 + (size_t)i * 64))[g];
    float4 a = ((const float4*)att)[g];

    float m = -1e30f, s = 0.f;
    float A0 = 0.f, A1 = 0.f, A2 = 0.f, A3 = 0.f;

    int base = e0;
    for (; base + 3 < e1; base += 4) {
        int idx1 = base + half;
        int idx2 = base + 2 + half;
        int j1 = g_col[idx1];
        int j2 = g_col[idx2];
        uint2 up1 = ((const uint2*)(g_xl1h + (size_t)j1 * 64))[g];
        uint2 up2 = ((const uint2*)(g_xl1h + (size_t)j2 * 64))[g];
        float2 u1a = __half22float2(*(__half2*)&up1.x);
        float2 u1b = __half22float2(*(__half2*)&up1.y);
        float2 u2a = __half22float2(*(__half2*)&up2.x);
        float2 u2b = __half22float2(*(__half2*)&up2.y);

        float t0 = u1a.x + r.x; t0 = (t0 > 0.f) ? t0 : 0.2f * t0;
        float t1 = u1a.y + r.y; t1 = (t1 > 0.f) ? t1 : 0.2f * t1;
        float t2 = u1b.x + r.z; t2 = (t2 > 0.f) ? t2 : 0.2f * t2;
        float t3 = u1b.y + r.w; t3 = (t3 > 0.f) ? t3 : 0.2f * t3;
        float p1 = t0 * a.x + t1 * a.y + t2 * a.z + t3 * a.w;
        float s0 = u2a.x + r.x; s0 = (s0 > 0.f) ? s0 : 0.2f * s0;
        float s1 = u2a.y + r.y; s1 = (s1 > 0.f) ? s1 : 0.2f * s1;
        float s2v = u2b.x + r.z; s2v = (s2v > 0.f) ? s2v : 0.2f * s2v;
        float s3 = u2b.y + r.w; s3 = (s3 > 0.f) ? s3 : 0.2f * s3;
        float p2 = s0 * a.x + s1 * a.y + s2v * a.z + s3 * a.w;
#pragma unroll
        for (int o = 1; o <= 8; o <<= 1) {
            p1 += __shfl_xor_sync(0xffffffffu, p1, o);
            p2 += __shfl_xor_sync(0xffffffffu, p2, o);
        }
        if (p1 > m) { float sc = __expf(m - p1); s *= sc; A0 *= sc; A1 *= sc; A2 *= sc; A3 *= sc; m = p1; }
        float w1 = __expf(p1 - m);
        s += w1; A0 += w1 * u1a.x; A1 += w1 * u1a.y; A2 += w1 * u1b.x; A3 += w1 * u1b.y;
        if (p2 > m) { float sc = __expf(m - p2); s *= sc; A0 *= sc; A1 *= sc; A2 *= sc; A3 *= sc; m = p2; }
        float w2 = __expf(p2 - m);
        s += w2; A0 += w2 * u2a.x; A1 += w2 * u2a.y; A2 += w2 * u2b.x; A3 += w2 * u2b.y;
    }
    for (; base < e1; base += 2) {
        int idx = base + half;
        bool act = idx < e1;
        int j = act ? g_col[idx] : 0;
        uint2 up = ((const uint2*)(g_xl1h + (size_t)j * 64))[g];
        float2 f01 = __half22float2(*(__half2*)&up.x);
        float2 f23 = __half22float2(*(__half2*)&up.y);

        float t0 = f01.x + r.x; t0 = (t0 > 0.f) ? t0 : 0.2f * t0;
        float t1 = f01.y + r.y; t1 = (t1 > 0.f) ? t1 : 0.2f * t1;
        float t2 = f23.x + r.z; t2 = (t2 > 0.f) ? t2 : 0.2f * t2;
        float t3 = f23.y + r.w; t3 = (t3 > 0.f) ? t3 : 0.2f * t3;
        float p = t0 * a.x + t1 * a.y + t2 * a.z + t3 * a.w;
#pragma unroll
        for (int o = 1; o <= 8; o <<= 1)
            p += __shfl_xor_sync(0xffffffffu, p, o);

        if (act) {
            if (p > m) {
                float sc = __expf(m - p);
                s *= sc; A0 *= sc; A1 *= sc; A2 *= sc; A3 *= sc;
                m = p;
            }
            float w = __expf(p - m);
            s += w;
            A0 += w * f01.x; A1 += w * f01.y; A2 += w * f23.x; A3 += w * f23.y;
        }
    }

    // merge the two half-states (xor 16) — both halves end with identical state
    {
        float mo  = __shfl_xor_sync(0xffffffffu, m, 16);
        float so  = __shfl_xor_sync(0xffffffffu, s, 16);
        float B0  = __shfl_xor_sync(0xffffffffu, A0, 16);
        float B1  = __shfl_xor_sync(0xffffffffu, A1, 16);
        float B2  = __shfl_xor_sync(0xffffffffu, A2, 16);
        float B3  = __shfl_xor_sync(0xffffffffu, A3, 16);
        float mn = fmaxf(m, mo);
        float c1 = __expf(m - mn);
        float c2 = __expf(mo - mn);
        s  = s * c1 + so * c2;
        A0 = A0 * c1 + B0 * c2;
        A1 = A1 * c1 + B1 * c2;
        A2 = A2 * c1 + B2 * c2;
        A3 = A3 * c1 + B3 * c2;
    }

    float inv = 1.0f / s;
    float4 bb = ((const float4*)b1)[g];
    float4 hl = ((const float4*)(g_h + (size_t)i * 64))[g];
    float o0 = A0 * inv + bb.x + hl.x;
    float o1 = A1 * inv + bb.y + hl.y;
    float o2 = A2 * inv + bb.z + hl.z;
    float o3 = A3 * inv + bb.w + hl.w;
    o0 = (o0 > 0.f) ? o0 : (__expf(o0) - 1.0f);   // ELU
    o1 = (o1 > 0.f) ? o1 : (__expf(o1) - 1.0f);
    o2 = (o2 > 0.f) ? o2 : (__expf(o2) - 1.0f);
    o3 = (o3 > 0.f) ? o3 : (__expf(o3) - 1.0f);

    // fused layer-2 transforms: partial dots over this lane's 4 channels
    const float2* WlV = (const float2*)Wl2;
    const float2* WrV = (const float2*)Wr2;
    const float2* WnV = (const float2*)Wlin2;
    int c = g * 4;
    float2 wl0 = WlV[c], wl1 = WlV[c + 1], wl2v = WlV[c + 2], wl3 = WlV[c + 3];
    float2 wr0 = WrV[c], wr1 = WrV[c + 1], wr2v = WrV[c + 2], wr3 = WrV[c + 3];
    float2 wn0 = WnV[c], wn1 = WnV[c + 1], wn2v = WnV[c + 2], wn3 = WnV[c + 3];
    float xl_0 = o0 * wl0.x + o1 * wl1.x + o2 * wl2v.x + o3 * wl3.x;
    float xl_1 = o0 * wl0.y + o1 * wl1.y + o2 * wl2v.y + o3 * wl3.y;
    float xr_0 = o0 * wr0.x + o1 * wr1.x + o2 * wr2v.x + o3 * wr3.x;
    float xr_1 = o0 * wr0.y + o1 * wr1.y + o2 * wr2v.y + o3 * wr3.y;
    float ln_0 = o0 * wn0.x + o1 * wn1.x + o2 * wn2v.x + o3 * wn3.x;
    float ln_1 = o0 * wn0.y + o1 * wn1.y + o2 * wn2v.y + o3 * wn3.y;
#pragma unroll
    for (int o = 1; o <= 8; o <<= 1) {
        xl_0 += __shfl_xor_sync(0xffffffffu, xl_0, o);
        xl_1 += __shfl_xor_sync(0xffffffffu, xl_1, o);
        xr_0 += __shfl_xor_sync(0xffffffffu, xr_0, o);
        xr_1 += __shfl_xor_sync(0xffffffffu, xr_1, o);
        ln_0 += __shfl_xor_sync(0xffffffffu, ln_0, o);
        ln_1 += __shfl_xor_sync(0xffffffffu, ln_1, o);
    }
    if (lane == 0) {
        ((float2*)g_xl2)[i] = make_float2(xl_0, xl_1);
        ((float2*)g_xr2)[i] = make_float2(xr_0, xr_1);
        ((float2*)g_lin2)[i] = make_float2(ln_0 + blin2[0], ln_1 + blin2[1]);
    }
}

// ---------------- K7: layer-2 attention, SINGLE PASS + log_softmax ----------------
__global__ void k_att2(const float* __restrict__ att2, const float* __restrict__ b2,
                       float* __restrict__ out) {
    int gt = blockIdx.x * blockDim.x + threadIdx.x;
    int i = gt >> 5;
    int lane = gt & 31;
    if (i >= Nn) return;

    int e0 = g_rowptr[i], e1 = g_rowptr[i + 1];
    const float2* xl2v = (const float2*)g_xl2;
    float2 xr = ((const float2*)g_xr2)[i];
    float a0 = att2[0], a1 = att2[1];

    float m = -1e30f, s = 0.f, A0 = 0.f, A1 = 0.f;
    for (int base = e0; base < e1; base += 32) {
        int idx = base + lane;
        if (idx < e1) {
            int j = g_col[idx];
            float2 xj = xl2v[j];
            float h0 = xj.x + xr.x; h0 = (h0 > 0.f) ? h0 : 0.2f * h0;
            float h1 = xj.y + xr.y; h1 = (h1 > 0.f) ? h1 : 0.2f * h1;
            float e = a0 * h0 + a1 * h1;
            if (e > m) { float sc = __expf(m - e); s *= sc; A0 *= sc; A1 *= sc; m = e; }
            float w = __expf(e - m);
            s += w; A0 += w * xj.x; A1 += w * xj.y;
        }
    }
#pragma unroll
    for (int o = 16; o; o >>= 1) {
        float mo  = __shfl_xor_sync(0xffffffffu, m, o);
        float so  = __shfl_xor_sync(0xffffffffu, s, o);
        float A0o = __shfl_xor_sync(0xffffffffu, A0, o);
        float A1o = __shfl_xor_sync(0xffffffffu, A1, o);
        float mn = fmaxf(m, mo);
        float sc1 = __expf(m - mn);
        float sc2 = __expf(mo - mn);
        s  = s * sc1 + so * sc2;
        A0 = A0 * sc1 + A0o * sc2;
        A1 = A1 * sc1 + A1o * sc2;
        m = mn;
    }

    if (lane == 0) {
        float inv = 1.0f / s;
        float2 ln = ((const float2*)g_lin2)[i];
        float z0 = A0 * inv + b2[0] + ln.x;
        float z1 = A1 * inv + b2[1] + ln.y;
        float zm = fmaxf(z0, z1);
        float l = zm + __logf(__expf(z0 - zm) + __expf(z1 - zm));
        ((float2*)out)[i] = make_float2(z0 - l, z1 - l);
    }
}

// ---------------- K8: edge_index passthrough as float32 values ----------------
__global__ void k_cast_edges(const int* __restrict__ ei, float* __restrict__ out, int n) {
    int i = blockIdx.x * blockDim.x + threadIdx.x;
    if (i < n) out[i] = (float)ei[i];
}

// ---------------- launcher: fork GEMM || CSR; gemm1 submitted 4th for ncu targeting ----------------
extern "C" void kernel_launch(void* const* d_in, const int* in_sizes, int n_in,
                              void* d_out, int out_size) {
    const float* x        = (const float*)d_in[0];
    const float* Wl1      = (const float*)d_in[2];
    const float* Wr1      = (const float*)d_in[3];
    const float* att1     = (const float*)d_in[4];
    const float* b1       = (const float*)d_in[5];
    const float* Wlin1    = (const float*)d_in[6];
    const float* blin1    = (const float*)d_in[7];
    const float* Wl2      = (const float*)d_in[8];
    const float* Wr2      = (const float*)d_in[9];
    const float* att2     = (const float*)d_in[10];
    const float* b2       = (const float*)d_in[11];
    const float* Wlin2    = (const float*)d_in[12];
    const float* blin2    = (const float*)d_in[13];
    float* out = (float*)d_out;

    long long tail_elems = (long long)out_size - (long long)Nn * 2;

    cudaFuncSetAttribute(k_gemm1, cudaFuncAttributeMaxDynamicSharedMemorySize, G1_SMEM);

    int nb = (Nn + 1023) / 1024;   // 98

    cudaStream_t s2;
    cudaStreamCreateWithFlags(&s2, cudaStreamNonBlocking);
    cudaEvent_t evFork, evJoin;
    cudaEventCreateWithFlags(&evFork, cudaEventDisableTiming);
    cudaEventCreateWithFlags(&evJoin, cudaEventDisableTiming);

    // fork s2 at entry: gemm1 depends only on inputs, regardless of submit position
    cudaEventRecord(evFork, 0);
    cudaStreamWaitEvent(s2, evFork, 0);

    // main stream CSR chain starts; gemm1 SUBMITTED 4th so ncu (-s5-c1) profiles it.
    k_init_deg<<<(Nn + 255) / 256, 256>>>();                         // sub 1
    k_deg<<<(Ee + 255) / 256, 256>>>((const int*)d_in[1]);           // sub 2
    k_scan1<<<nb, 1024>>>();                                         // sub 3
    k_gemm1<<<152, G1_THREADS, G1_SMEM, s2>>>(x, Wl1, Wr1, Wlin1, blin1);  // sub 4 <- profiled
    cudaEventRecord(evJoin, s2);
    k_scan2<<<1, 128>>>(nb);                                         // sub 5
    k_scan3<<<(Nn + 255) / 256, 256>>>();                            // sub 6
    k_scatter<<<(ET + 255) / 256, 256>>>((const int*)d_in[1]);       // sub 7
    if (tail_elems > 0) {
        int n = (tail_elems < (long long)2 * Ee) ? (int)tail_elems : 2 * Ee;
        k_cast_edges<<<(n + 255) / 256, 256>>>(
            (const int*)d_in[1], out + (size_t)Nn * 2, n);
    }

    // join: attention needs both GEMM outputs and CSR
    cudaStreamWaitEvent(0, evJoin, 0);
    k_att1<<<(Nn * 32 + 255) / 256, 256>>>(att1, b1, Wl2, Wr2, Wlin2, blin2);
    k_att2<<<(Nn * 32 + 255) / 256, 256>>>(att2, b2, out);

    cudaEventDestroy(evFork);
    cudaEventDestroy(evJoin);
    cudaStreamDestroy(s2);
}